// round 4
// baseline (speedup 1.0000x reference)
#include <cuda_runtime.h>
#include <math.h>

#define N_TOK 384
#define TDIM 768
#define VDIM 768
#define CDIM 1536
#define FF_DIM 2048
#define NH 4
#define NLAYERS 2

// ---------------- scratch (no allocations allowed) ----------------
#define OFF_X   0LL
#define OFF_X2  589824LL
#define OFF_QKV 1179648LL
#define OFF_SC  2949120LL
#define OFF_O   3538944LL
#define OFF_Y   4128768LL
#define OFF_H   4718592LL
#define OFF_A   5505024LL
#define OFF_C   5505792LL
#define OFF_RC  5506560LL
#define OFF_RL  5506944LL
#define OFF_CL  5507328LL
#define BUF_TOTAL 5507712LL

__device__ float g_buf[BUF_TOTAL];

// ---------------- PDL helpers ----------------
__device__ __forceinline__ void pdl_wait() {
    asm volatile("griddepcontrol.wait;" ::: "memory");
}
__device__ __forceinline__ void pdl_go() {
    asm volatile("griddepcontrol.launch_dependents;" ::: "memory");
}

// ---------------- misc helpers ----------------
__device__ __forceinline__ unsigned f2tf(float x) {
    unsigned u;
    asm("cvt.rna.tf32.f32 %0, %1;" : "=r"(u) : "f"(x));
    return u;
}

__device__ __forceinline__ void mma8(float* c, const unsigned* a, const unsigned* b) {
    asm volatile(
        "mma.sync.aligned.m16n8k8.row.col.f32.tf32.tf32.f32 "
        "{%0,%1,%2,%3},{%4,%5,%6,%7},{%8,%9},{%0,%1,%2,%3};"
        : "+f"(c[0]), "+f"(c[1]), "+f"(c[2]), "+f"(c[3])
        : "r"(a[0]), "r"(a[1]), "r"(a[2]), "r"(a[3]), "r"(b[0]), "r"(b[1]));
}

__device__ __forceinline__ void cpa16(unsigned dst, const float* src) {
    asm volatile("cp.async.cg.shared.global [%0], [%1], 16;" :: "r"(dst), "l"(src));
}
__device__ __forceinline__ void cpa_commit() {
    asm volatile("cp.async.commit_group;");
}
template <int N>
__device__ __forceinline__ void cpa_wait() {
    asm volatile("cp.async.wait_group %0;" :: "n"(N));
}

__global__ void copy_k(float* __restrict__ dst, const float* __restrict__ src, int n) {
    pdl_wait();
    pdl_go();
    int i = blockIdx.x * blockDim.x + threadIdx.x;
    if (i < n) dst[i] = src[i];
}

__global__ void concat_k(float* __restrict__ dst, const float* __restrict__ te,
                         const float* __restrict__ vis) {
    pdl_wait();
    pdl_go();
    int i = blockIdx.x * blockDim.x + threadIdx.x;
    if (i < N_TOK * CDIM) {
        int r = i / CDIM, c = i % CDIM;
        dst[i] = (c < TDIM) ? te[r * TDIM + c] : vis[r * VDIM + (c - TDIM)];
    }
}

// ============ NT GEMM: C = alpha*A(MxK,row)@W(NxK,row)^T + bias =============
// TM x 128 block tile (TM=64 or 32), BK=16, 256 threads = 8 warps.
// 3-stage cp.async pipeline. If w_const, weight prefetch overlaps prior kernel
// via PDL (issued before griddepcontrol.wait).
#define SPAD 20

template <int TM>
__global__ void __launch_bounds__(256) tf32_nt(
    const float* __restrict__ A, int lda, long long aZ,
    const float* __restrict__ W, int ldw, long long wZ,
    const float* __restrict__ Bias,
    float* __restrict__ C, int ldc, long long cZ,
    int K, float alpha, int relu, int w_const)
{
    constexpr int MT = TM / 32;          // m16 tiles per warp tile (2 or 1)
    constexpr int AS = TM * SPAD;
    constexpr int BS = 128 * SPAD;

    A += blockIdx.z * aZ; W += blockIdx.z * wZ; C += blockIdx.z * cZ;
    __shared__ float As[3][AS];
    __shared__ float Bs[3][BS];

    int tid = threadIdx.x;
    int warp = tid >> 5, lane = tid & 31;
    int g = lane >> 2, tg = lane & 3;
    int wm = (warp >> 2) * (TM / 2);
    int wn = (warp & 3) * 32;
    int m0 = blockIdx.y * TM, n0 = blockIdx.x * 128;

    // A: TM rows x 16 cols. TM64: all 256 threads, 1 chunk. TM32: tid<128.
    int lrowA = tid >> 2;
    int q4 = (tid & 3) * 4;
    bool aAct = (TM == 64) || (tid < 128);
    const float* aSrc = A + (long long)(m0 + lrowA) * lda + q4;
    unsigned aDst = (unsigned)__cvta_generic_to_shared(&As[0][lrowA * SPAD + q4]);

    // B: 128 rows x 16 cols, 2 chunks per thread (all 256).
    int rowB = tid >> 1;
    int cB = (tid & 1) * 8;
    const float* bSrc = W + (long long)(n0 + rowB) * ldw + cB;
    unsigned bDst = (unsigned)__cvta_generic_to_shared(&Bs[0][rowB * SPAD + cB]);

    int ntile = K / 16;
    float acc[MT][4][4] = {};

    // ---- prologue with PDL overlap ----
    if (w_const) {
        // weights are pure inputs: prefetch before the dependency wait
#pragma unroll
        for (int s = 0; s < 2; s++) {
            cpa16(bDst + s * BS * 4, bSrc + s * 16);
            cpa16(bDst + s * BS * 4 + 16, bSrc + s * 16 + 4);
        }
        pdl_wait();
#pragma unroll
        for (int s = 0; s < 2; s++) {
            if (aAct) cpa16(aDst + s * AS * 4, aSrc + s * 16);
            cpa_commit();
        }
    } else {
        pdl_wait();
#pragma unroll
        for (int s = 0; s < 2; s++) {
            cpa16(bDst + s * BS * 4, bSrc + s * 16);
            cpa16(bDst + s * BS * 4 + 16, bSrc + s * 16 + 4);
            if (aAct) cpa16(aDst + s * AS * 4, aSrc + s * 16);
            cpa_commit();
        }
    }

    for (int it = 0; it < ntile; it++) {
        cpa_wait<1>();
        __syncthreads();
        if (it + 2 < ntile) {
            int s = (it + 2) % 3;
            int k0 = (it + 2) * 16;
            cpa16(bDst + s * BS * 4, bSrc + k0);
            cpa16(bDst + s * BS * 4 + 16, bSrc + k0 + 4);
            if (aAct) cpa16(aDst + s * AS * 4, aSrc + k0);
        }
        cpa_commit();
        const unsigned* Ab = (const unsigned*)As[it % 3];
        const unsigned* Bb = (const unsigned*)Bs[it % 3];
#pragma unroll
        for (int ks = 0; ks < 2; ks++) {
            int kb = ks * 8;
            unsigned a[MT][4], b[4][2];
#pragma unroll
            for (int mt = 0; mt < MT; mt++) {
                const unsigned* base = &Ab[(wm + mt * 16 + g) * SPAD + kb + tg];
                a[mt][0] = base[0];
                a[mt][1] = base[8 * SPAD];
                a[mt][2] = base[4];
                a[mt][3] = base[8 * SPAD + 4];
            }
#pragma unroll
            for (int nt = 0; nt < 4; nt++) {
                const unsigned* base = &Bb[(wn + nt * 8 + g) * SPAD + kb + tg];
                b[nt][0] = base[0];
                b[nt][1] = base[4];
            }
#pragma unroll
            for (int mt = 0; mt < MT; mt++)
#pragma unroll
                for (int nt = 0; nt < 4; nt++)
                    mma8(acc[mt][nt], a[mt], b[nt]);
        }
    }

    pdl_go();

#pragma unroll
    for (int mt = 0; mt < MT; mt++) {
#pragma unroll
        for (int nt = 0; nt < 4; nt++) {
            int col = n0 + wn + nt * 8 + 2 * tg;
            float b0 = 0.f, b1 = 0.f;
            if (Bias) { b0 = Bias[col]; b1 = Bias[col + 1]; }
            int row = m0 + wm + mt * 16 + g;
            float2 v0, v1;
            v0.x = acc[mt][nt][0] * alpha + b0;
            v0.y = acc[mt][nt][1] * alpha + b1;
            v1.x = acc[mt][nt][2] * alpha + b0;
            v1.y = acc[mt][nt][3] * alpha + b1;
            if (relu) {
                v0.x = fmaxf(v0.x, 0.f); v0.y = fmaxf(v0.y, 0.f);
                v1.x = fmaxf(v1.x, 0.f); v1.y = fmaxf(v1.y, 0.f);
            }
            *(float2*)&C[(long long)row * ldc + col] = v0;
            *(float2*)&C[(long long)(row + 8) * ldc + col] = v1;
        }
    }
}

// ============ NN GEMM: C = A(MxK,row) @ B(KxN,row), batched via z ============
__global__ void __launch_bounds__(128) tf32_nn(
    const float* __restrict__ A, int lda, long long aZ,
    const float* __restrict__ B, int ldb, long long bZ,
    float* __restrict__ C, int ldc, long long cZ,
    int K)
{
    pdl_wait();
    A += blockIdx.z * aZ; B += blockIdx.z * bZ; C += blockIdx.z * cZ;
    __shared__ unsigned As[2][64 * SPAD];
    __shared__ unsigned Bs[2][64 * SPAD];
    int tid = threadIdx.x;
    int warp = tid >> 5, lane = tid & 31;
    int g = lane >> 2, tg = lane & 3;
    int wm = (warp >> 1) * 32, wn = (warp & 1) * 32;
    int m0 = blockIdx.y * 64, n0 = blockIdx.x * 64;

    int lrow = tid >> 1;
    int lcol = (tid & 1) * 8;
    const float* Ap = A + (long long)(m0 + lrow) * lda + lcol;
    int sidx = lrow * SPAD + lcol;

    int f0 = tid * 2;
    int bk0 = f0 >> 4, bc0 = (f0 & 15) * 4;
    int bk1 = (f0 + 1) >> 4, bc1 = ((f0 + 1) & 15) * 4;
    const float* Bp0 = B + (long long)bk0 * ldb + n0 + bc0;
    const float* Bp1 = B + (long long)bk1 * ldb + n0 + bc1;

    float acc[2][4][4] = {};
    int ntile = K / 16;
    {
        float4 a0 = *(const float4*)(Ap);
        float4 a1 = *(const float4*)(Ap + 4);
        float4 v0 = *(const float4*)(Bp0);
        float4 v1 = *(const float4*)(Bp1);
        *(uint4*)&As[0][sidx]     = make_uint4(f2tf(a0.x), f2tf(a0.y), f2tf(a0.z), f2tf(a0.w));
        *(uint4*)&As[0][sidx + 4] = make_uint4(f2tf(a1.x), f2tf(a1.y), f2tf(a1.z), f2tf(a1.w));
        Bs[0][(bc0 + 0) * SPAD + bk0] = f2tf(v0.x);
        Bs[0][(bc0 + 1) * SPAD + bk0] = f2tf(v0.y);
        Bs[0][(bc0 + 2) * SPAD + bk0] = f2tf(v0.z);
        Bs[0][(bc0 + 3) * SPAD + bk0] = f2tf(v0.w);
        Bs[0][(bc1 + 0) * SPAD + bk1] = f2tf(v1.x);
        Bs[0][(bc1 + 1) * SPAD + bk1] = f2tf(v1.y);
        Bs[0][(bc1 + 2) * SPAD + bk1] = f2tf(v1.z);
        Bs[0][(bc1 + 3) * SPAD + bk1] = f2tf(v1.w);
    }
    __syncthreads();
    int p = 0;
    for (int it = 0; it < ntile; it++) {
        float4 na0, na1, nv0, nv1;
        if (it + 1 < ntile) {
            int ko = (it + 1) * 16;
            na0 = *(const float4*)(Ap + ko);
            na1 = *(const float4*)(Ap + ko + 4);
            nv0 = *(const float4*)(Bp0 + (long long)ko * ldb);
            nv1 = *(const float4*)(Bp1 + (long long)ko * ldb);
        }
#pragma unroll
        for (int ks = 0; ks < 2; ks++) {
            int kb = ks * 8;
            unsigned a[2][4], b[4][2];
#pragma unroll
            for (int mt = 0; mt < 2; mt++) {
                const unsigned* base = &As[p][(wm + mt * 16 + g) * SPAD + kb + tg];
                a[mt][0] = base[0];
                a[mt][1] = base[8 * SPAD];
                a[mt][2] = base[4];
                a[mt][3] = base[8 * SPAD + 4];
            }
#pragma unroll
            for (int nt = 0; nt < 4; nt++) {
                const unsigned* base = &Bs[p][(wn + nt * 8 + g) * SPAD + kb + tg];
                b[nt][0] = base[0];
                b[nt][1] = base[4];
            }
#pragma unroll
            for (int mt = 0; mt < 2; mt++)
#pragma unroll
                for (int nt = 0; nt < 4; nt++)
                    mma8(acc[mt][nt], a[mt], b[nt]);
        }
        if (it + 1 < ntile) {
            int q = p ^ 1;
            *(uint4*)&As[q][sidx]     = make_uint4(f2tf(na0.x), f2tf(na0.y), f2tf(na0.z), f2tf(na0.w));
            *(uint4*)&As[q][sidx + 4] = make_uint4(f2tf(na1.x), f2tf(na1.y), f2tf(na1.z), f2tf(na1.w));
            Bs[q][(bc0 + 0) * SPAD + bk0] = f2tf(nv0.x);
            Bs[q][(bc0 + 1) * SPAD + bk0] = f2tf(nv0.y);
            Bs[q][(bc0 + 2) * SPAD + bk0] = f2tf(nv0.z);
            Bs[q][(bc0 + 3) * SPAD + bk0] = f2tf(nv0.w);
            Bs[q][(bc1 + 0) * SPAD + bk1] = f2tf(nv1.x);
            Bs[q][(bc1 + 1) * SPAD + bk1] = f2tf(nv1.y);
            Bs[q][(bc1 + 2) * SPAD + bk1] = f2tf(nv1.z);
            Bs[q][(bc1 + 3) * SPAD + bk1] = f2tf(nv1.w);
        }
        __syncthreads();
        p ^= 1;
    }

    pdl_go();

#pragma unroll
    for (int mt = 0; mt < 2; mt++) {
#pragma unroll
        for (int nt = 0; nt < 4; nt++) {
            int col = n0 + wn + nt * 8 + 2 * tg;
            int row = m0 + wm + mt * 16 + g;
            float2 v0, v1;
            v0.x = acc[mt][nt][0]; v0.y = acc[mt][nt][1];
            v1.x = acc[mt][nt][2]; v1.y = acc[mt][nt][3];
            *(float2*)&C[(long long)row * ldc + col] = v0;
            *(float2*)&C[(long long)(row + 8) * ldc + col] = v1;
        }
    }
}

// ---------------- row softmax ----------------
__global__ void softmax_rows(float* __restrict__ S, int n) {
    pdl_wait();
    pdl_go();
    float* row = S + (long long)blockIdx.x * n;
    __shared__ float red[128];
    int tid = threadIdx.x;
    float m = -1e30f;
    for (int j = tid; j < n; j += 128) m = fmaxf(m, row[j]);
    red[tid] = m; __syncthreads();
    for (int off = 64; off; off >>= 1) {
        if (tid < off) red[tid] = fmaxf(red[tid], red[tid + off]);
        __syncthreads();
    }
    m = red[0]; __syncthreads();
    float s = 0.f;
    for (int j = tid; j < n; j += 128) { float e = expf(row[j] - m); row[j] = e; s += e; }
    red[tid] = s; __syncthreads();
    for (int off = 64; off; off >>= 1) {
        if (tid < off) red[tid] += red[tid + off];
        __syncthreads();
    }
    float inv = 1.0f / red[0];
    for (int j = tid; j < n; j += 128) row[j] *= inv;
}

// ---------------- x = LN(x + delta) ----------------
__global__ void ln_res_kernel(float* __restrict__ x, const float* __restrict__ delta,
                              const float* __restrict__ s, const float* __restrict__ b, int d) {
    pdl_wait();
    pdl_go();
    float* xr = x + (long long)blockIdx.x * d;
    const float* dr = delta + (long long)blockIdx.x * d;
    __shared__ float red[256];
    int tid = threadIdx.x;
    float sum = 0.f;
    for (int j = tid; j < d; j += 256) { float v = xr[j] + dr[j]; xr[j] = v; sum += v; }
    red[tid] = sum; __syncthreads();
    for (int off = 128; off; off >>= 1) {
        if (tid < off) red[tid] += red[tid + off];
        __syncthreads();
    }
    float mean = red[0] / d; __syncthreads();
    float s2 = 0.f;
    for (int j = tid; j < d; j += 256) { float v = xr[j] - mean; s2 += v * v; }
    red[tid] = s2; __syncthreads();
    for (int off = 128; off; off >>= 1) {
        if (tid < off) red[tid] += red[tid + off];
        __syncthreads();
    }
    float inv = rsqrtf(red[0] / d + 1e-5f);
    __syncthreads();
    for (int j = tid; j < d; j += 256) xr[j] = (xr[j] - mean) * inv * s[j] + b[j];
}

// ---------------- final linear ----------------
__global__ void lin_kernel(const float* __restrict__ x, const float* __restrict__ w,
                           const float* __restrict__ b, float* __restrict__ a,
                           float* __restrict__ c) {
    pdl_wait();
    pdl_go();
    int i = blockIdx.x;
    const float* xr = x + (long long)i * CDIM;
    __shared__ float red[4][256];
    int tid = threadIdx.x;
    float s0 = 0, s1 = 0, s2 = 0, s3 = 0;
    for (int k = tid; k < CDIM; k += 256) {
        float xv = xr[k];
        s0 += xv * w[k];
        s1 += xv * w[2 * CDIM + k];
        s2 += xv * w[CDIM + k];
        s3 += xv * w[2 * CDIM + CDIM + k];
    }
    red[0][tid] = s0; red[1][tid] = s1; red[2][tid] = s2; red[3][tid] = s3;
    __syncthreads();
    for (int off = 128; off; off >>= 1) {
        if (tid < off) {
            red[0][tid] += red[0][tid + off];
            red[1][tid] += red[1][tid + off];
            red[2][tid] += red[2][tid + off];
            red[3][tid] += red[3][tid + off];
        }
        __syncthreads();
    }
    if (tid == 0) {
        a[2 * i]     = red[0][0] + b[0];
        a[2 * i + 1] = red[1][0] + b[1];
        c[2 * i]     = red[2][0];
        c[2 * i + 1] = red[3][0];
    }
}

// ---------------- pairwise probs + per-row loss partials ----------------
__global__ void pair_kernel(const float* __restrict__ a, const float* __restrict__ c,
                            const int* __restrict__ gt, float* __restrict__ probs,
                            float* __restrict__ rowcell, float* __restrict__ rowlink) {
    pdl_wait();
    pdl_go();
    int i = blockIdx.x, j = threadIdx.x;
    float l0 = a[2 * i] + c[2 * j];
    float l1 = a[2 * i + 1] + c[2 * j + 1];
    float m = fmaxf(l0, l1);
    float e0 = expf(l0 - m), e1 = expf(l1 - m);
    float inv = 1.0f / (e0 + e1);
    float p0 = e0 * inv, p1 = e1 * inv;
    long long idx = ((long long)i * N_TOK + j) * 2;
    probs[idx] = p0; probs[idx + 1] = p1;
    float mm = fmaxf(p0, p1);
    float lse = mm + logf(expf(p0 - mm) + expf(p1 - mm));
    float pg = gt[i * N_TOK + j] ? p1 : p0;
    float cell = lse - pg;

    __shared__ float red[512];
    red[j] = cell;
    if (j < 128) red[384 + j] = 0.f;
    __syncthreads();
    for (int off = 256; off; off >>= 1) {
        if (j < off) red[j] += red[j + off];
        __syncthreads();
    }
    if (j == 0) rowcell[i] = red[0];
    __syncthreads();
    red[j] = p1;
    if (j < 128) red[384 + j] = 0.f;
    __syncthreads();
    for (int off = 256; off; off >>= 1) {
        if (j < off) red[j] += red[j + off];
        __syncthreads();
    }
    if (j == 0) rowlink[i] = red[0];
}

__global__ void col_kernel(const float* __restrict__ probs, float* __restrict__ collink) {
    pdl_wait();
    pdl_go();
    int j = blockIdx.x; int tid = threadIdx.x;
    float s = 0.f;
    for (int i = tid; i < N_TOK; i += 128) s += probs[((long long)i * N_TOK + j) * 2 + 1];
    __shared__ float red[128];
    red[tid] = s; __syncthreads();
    for (int off = 64; off; off >>= 1) {
        if (tid < off) red[tid] += red[tid + off];
        __syncthreads();
    }
    if (tid == 0) collink[j] = red[0];
}

__global__ void final_kernel(const float* __restrict__ rowcell, const float* __restrict__ rowlink,
                             const float* __restrict__ collink, float* __restrict__ out,
                             int out_size) {
    pdl_wait();
    __shared__ float r1[512], r2[512];
    int tid = threadIdx.x;
    r1[tid] = (tid < N_TOK) ? rowcell[tid] : 0.f;
    r2[tid] = (tid < N_TOK - 1) ? fabsf(rowlink[tid] + collink[tid] - 1.0f) : 0.f;
    __syncthreads();
    for (int off = 256; off; off >>= 1) {
        if (tid < off) { r1[tid] += r1[tid + off]; r2[tid] += r2[tid + off]; }
        __syncthreads();
    }
    if (tid == 0 && out_size >= N_TOK * N_TOK * 2 + 2) {
        out[N_TOK * N_TOK * 2]     = r1[0] / (float)N_TOK;
        out[N_TOK * N_TOK * 2 + 1] = r2[0];
    }
}

// ---------------- host orchestration ----------------
static cudaLaunchAttribute g_pdl_attr[1];

static inline cudaLaunchConfig_t mkcfg(dim3 g, dim3 b) {
    cudaLaunchConfig_t c = {};
    c.gridDim = g; c.blockDim = b; c.dynamicSmemBytes = 0; c.stream = 0;
    g_pdl_attr[0].id = cudaLaunchAttributeProgrammaticStreamSerialization;
    g_pdl_attr[0].val.programmaticStreamSerializationAllowed = 1;
    c.attrs = g_pdl_attr; c.numAttrs = 1;
    return c;
}

template <typename F, typename... Args>
static inline void pl(F f, dim3 g, dim3 b, Args... args) {
    cudaLaunchConfig_t c = mkcfg(g, b);
    cudaLaunchKernelEx(&c, f, args...);
}

// NT dispatch: pick TM=64 when grid fills the chip, else TM=32.
static void nt(const float* A, int lda, long long aZ,
               const float* W, int ldw, long long wZ,
               const float* Bias, float* C, int ldc, long long cZ,
               int M, int N, int K, float alpha, int relu, int w_const, int nz) {
    int ctas64 = (N / 128) * (M / 64) * nz;
    if (ctas64 >= 148) {
        pl(tf32_nt<64>, dim3(N / 128, M / 64, nz), dim3(256),
           A, lda, aZ, W, ldw, wZ, Bias, C, ldc, cZ, K, alpha, relu, w_const);
    } else {
        pl(tf32_nt<32>, dim3(N / 128, M / 32, nz), dim3(256),
           A, lda, aZ, W, ldw, wZ, Bias, C, ldc, cZ, K, alpha, relu, w_const);
    }
}

struct EncWeights {
    const float *qkv_w, *qkv_b, *out_w, *out_b, *ln1_s, *ln1_b;
    const float *ff1_w, *ff1_b, *ff2_w, *ff2_b, *ln2_s, *ln2_b;
};

static void run_encoder(float* x, int d, const EncWeights& w,
                        float* qkv, float* sc, float* o, float* y, float* h) {
    const int M = N_TOK;
    const int hd = d / NH;
    const float scale = 1.0f / sqrtf((float)hd);
    for (int l = 0; l < NLAYERS; l++) {
        const float* Wq = w.qkv_w + (long long)l * 3 * d * d;
        const float* Bq = w.qkv_b + (long long)l * 3 * d;
        // qkv = x @ Wq^T + Bq
        nt(x, d, 0, Wq, d, 0, Bq, qkv, 3 * d, 0, M, 3 * d, d, 1.f, 0, 1, 1);
        // scores[h] = Q_h @ K_h^T * scale (batched over heads); both operands dependent
        nt(qkv, 3 * d, hd, qkv + d, 3 * d, hd, (const float*)0,
           sc, M, (long long)M * M, M, M, hd, scale, 0, 0, NH);
        pl(softmax_rows, dim3(NH * M), dim3(128), sc, M);
        // o[:, h*hd:] = attn_h @ V_h (batched)
        pl(tf32_nn, dim3(hd / 64, M / 64, NH), dim3(128),
           sc, M, (long long)M * M, qkv + 2 * d, (long long)3 * d, (long long)hd,
           o, d, (long long)hd, M);
        // y = o @ out_w^T + out_b
        nt(o, d, 0, w.out_w + (long long)l * d * d, d, 0, w.out_b + (long long)l * d,
           y, d, 0, M, d, d, 1.f, 0, 1, 1);
        pl(ln_res_kernel, dim3(M), dim3(256),
           x, (const float*)y, w.ln1_s + (long long)l * d, w.ln1_b + (long long)l * d, d);
        // h = relu(x @ ff1^T + b1)
        nt(x, d, 0, w.ff1_w + (long long)l * FF_DIM * d, d, 0, w.ff1_b + (long long)l * FF_DIM,
           h, FF_DIM, 0, M, FF_DIM, d, 1.f, 1, 1, 1);
        // y = h @ ff2^T + b2
        nt(h, FF_DIM, 0, w.ff2_w + (long long)l * d * FF_DIM, FF_DIM, 0, w.ff2_b + (long long)l * d,
           y, d, 0, M, d, FF_DIM, 1.f, 0, 1, 1);
        pl(ln_res_kernel, dim3(M), dim3(256),
           x, (const float*)y, w.ln2_s + (long long)l * d, w.ln2_b + (long long)l * d, d);
    }
}

extern "C" void kernel_launch(void* const* d_in, const int* in_sizes, int n_in,
                              void* d_out, int out_size) {
    const float* text   = (const float*)d_in[0];
    const float* vision = (const float*)d_in[1];
    const int*   gt     = (const int*)d_in[2];

    EncWeights tw = {
        (const float*)d_in[3],  (const float*)d_in[4],  (const float*)d_in[5],
        (const float*)d_in[6],  (const float*)d_in[7],  (const float*)d_in[8],
        (const float*)d_in[9],  (const float*)d_in[10], (const float*)d_in[11],
        (const float*)d_in[12], (const float*)d_in[13], (const float*)d_in[14]
    };
    EncWeights cw = {
        (const float*)d_in[15], (const float*)d_in[16], (const float*)d_in[17],
        (const float*)d_in[18], (const float*)d_in[19], (const float*)d_in[20],
        (const float*)d_in[21], (const float*)d_in[22], (const float*)d_in[23],
        (const float*)d_in[24], (const float*)d_in[25], (const float*)d_in[26]
    };
    const float* lin_w = (const float*)d_in[27];
    const float* lin_b = (const float*)d_in[28];

    float* buf = nullptr;
    cudaGetSymbolAddress((void**)&buf, g_buf);
    float* x    = buf + OFF_X;
    float* x2   = buf + OFF_X2;
    float* qkv  = buf + OFF_QKV;
    float* sc   = buf + OFF_SC;
    float* o    = buf + OFF_O;
    float* y    = buf + OFF_Y;
    float* h    = buf + OFF_H;
    float* ga   = buf + OFF_A;
    float* gc   = buf + OFF_C;
    float* rcel = buf + OFF_RC;
    float* rlnk = buf + OFF_RL;
    float* clnk = buf + OFF_CL;

    pl(copy_k, dim3((N_TOK * TDIM + 255) / 256), dim3(256), x, text, N_TOK * TDIM);
    run_encoder(x, TDIM, tw, qkv, sc, o, y, h);

    pl(concat_k, dim3((N_TOK * CDIM + 255) / 256), dim3(256), x2, (const float*)x, vision);
    run_encoder(x2, CDIM, cw, qkv, sc, o, y, h);

    pl(lin_kernel, dim3(N_TOK), dim3(256), (const float*)x2, lin_w, lin_b, ga, gc);

    float* out = (float*)d_out;
    pl(pair_kernel, dim3(N_TOK), dim3(N_TOK),
       (const float*)ga, (const float*)gc, gt, out, rcel, rlnk);
    pl(col_kernel, dim3(N_TOK), dim3(128), (const float*)out, clnk);
    pl(final_kernel, dim3(1), dim3(512),
       (const float*)rcel, (const float*)rlnk, (const float*)clnk, out, out_size);
}

// round 5
// speedup vs baseline: 1.8425x; 1.8425x over previous
#include <cuda_runtime.h>
#include <cuda_fp16.h>
#include <math.h>

#define N_TOK 384
#define TDIM 768
#define VDIM 768
#define CDIM 1536
#define FF_DIM 2048
#define NH 4
#define NLAYERS 2

// ---------------- fp32 scratch ----------------
#define OFF_X   0LL
#define OFF_X2  589824LL
#define OFF_QKV 1179648LL
#define OFF_SC  2949120LL
#define OFF_Y   4128768LL
#define OFF_A   5505024LL
#define OFF_C   5505792LL
#define OFF_RC  5506560LL
#define OFF_RL  5506944LL
#define OFF_CL  5507328LL
#define BUF_TOTAL 5507712LL
__device__ float g_buf[BUF_TOTAL];

// ---------------- fp16 scratch (weights converted once + activation shadows) ----------
#define HW_TQKV 0LL
#define HW_TOUT 3538944LL
#define HW_TFF1 4718592LL
#define HW_TFF2 7864320LL
#define HW_CQKV 11010048LL
#define HW_COUT 25165824LL
#define HW_CFF1 29884416LL
#define HW_CFF2 36175872LL
#define HA_QKV  42467328LL
#define HA_X    44236800LL
#define HA_O    44826624LL
#define HA_H    45416448LL
#define HBUF_TOTAL 46202880LL
__device__ __half g_hbuf[HBUF_TOTAL];

// ---------------- helpers ----------------
__device__ __forceinline__ unsigned f2tf(float x) {
    unsigned u;
    asm("cvt.rna.tf32.f32 %0, %1;" : "=r"(u) : "f"(x));
    return u;
}

__device__ __forceinline__ void mma8(float* c, const unsigned* a, const unsigned* b) {
    asm volatile(
        "mma.sync.aligned.m16n8k8.row.col.f32.tf32.tf32.f32 "
        "{%0,%1,%2,%3},{%4,%5,%6,%7},{%8,%9},{%0,%1,%2,%3};"
        : "+f"(c[0]), "+f"(c[1]), "+f"(c[2]), "+f"(c[3])
        : "r"(a[0]), "r"(a[1]), "r"(a[2]), "r"(a[3]), "r"(b[0]), "r"(b[1]));
}

__device__ __forceinline__ void mma16h(float* c, const unsigned* a, const unsigned* b) {
    asm volatile(
        "mma.sync.aligned.m16n8k16.row.col.f32.f16.f16.f32 "
        "{%0,%1,%2,%3},{%4,%5,%6,%7},{%8,%9},{%0,%1,%2,%3};"
        : "+f"(c[0]), "+f"(c[1]), "+f"(c[2]), "+f"(c[3])
        : "r"(a[0]), "r"(a[1]), "r"(a[2]), "r"(a[3]), "r"(b[0]), "r"(b[1]));
}

__device__ __forceinline__ void cpa16(unsigned dst, const void* src) {
    asm volatile("cp.async.cg.shared.global [%0], [%1], 16;" :: "r"(dst), "l"(src));
}
__device__ __forceinline__ void cpa_commit() { asm volatile("cp.async.commit_group;"); }
template <int N>
__device__ __forceinline__ void cpa_wait() {
    asm volatile("cp.async.wait_group %0;" :: "n"(N));
}

// ---------------- small kernels ----------------
__global__ void conv_k(__half* __restrict__ dst, const float* __restrict__ src, int n4) {
    int i = blockIdx.x * blockDim.x + threadIdx.x;
    if (i < n4) {
        float4 v = ((const float4*)src)[i];
        __half2* d = (__half2*)dst + i * 2;
        d[0] = __floats2half2_rn(v.x, v.y);
        d[1] = __floats2half2_rn(v.z, v.w);
    }
}

__global__ void copy_k(float* __restrict__ dst, __half* __restrict__ dsth,
                       const float* __restrict__ src, int n) {
    int i = blockIdx.x * blockDim.x + threadIdx.x;
    if (i < n) { float v = src[i]; dst[i] = v; dsth[i] = __float2half(v); }
}

__global__ void concat_k(float* __restrict__ dst, __half* __restrict__ dsth,
                         const float* __restrict__ te, const float* __restrict__ vis) {
    int i = blockIdx.x * blockDim.x + threadIdx.x;
    if (i < N_TOK * CDIM) {
        int r = i / CDIM, c = i % CDIM;
        float v = (c < TDIM) ? te[r * TDIM + c] : vis[r * VDIM + (c - TDIM)];
        dst[i] = v; dsth[i] = __float2half(v);
    }
}

// ============ fp16 NT GEMM: C = alpha*A(MxK,row)@W(NxK,row)^T + bias ========
// 64x128 tile, BK=32, 256 threads = 8 warps (2x4), warp tile 32x32.
// 3-stage cp.async. Outputs optionally fp32 (C32) and/or fp16 (C16).
#define HPAD 40
#define H_AS (64 * HPAD)
#define H_BS (128 * HPAD)

__global__ void __launch_bounds__(256) h16_nt(
    const __half* __restrict__ A, int lda, long long aZ,
    const __half* __restrict__ W, int ldw, long long wZ,
    const float* __restrict__ Bias,
    float* __restrict__ C32, __half* __restrict__ C16,
    int ldc, long long cZ,
    int K, float alpha, int relu)
{
    A += blockIdx.z * aZ; W += blockIdx.z * wZ;
    __shared__ __half As[3][H_AS];
    __shared__ __half Bs[3][H_BS];

    int tid = threadIdx.x;
    int warp = tid >> 5, lane = tid & 31;
    int g = lane >> 2, tg = lane & 3;
    int wm = (warp >> 2) * 32, wn = (warp & 3) * 32;
    int m0 = blockIdx.y * 64, n0 = blockIdx.x * 128;

    // A: 64 rows x 32 halves/stage = 256 x 16B chunks; one per thread.
    int rowA = tid >> 2, kA = (tid & 3) * 8;
    const __half* aSrc = A + (long long)(m0 + rowA) * lda + kA;
    unsigned aDst = (unsigned)__cvta_generic_to_shared(&As[0][rowA * HPAD + kA]);
    // B: 128 rows x 32 halves/stage = 512 chunks; two per thread.
    int c0 = tid * 2;
    int rowB0 = c0 >> 2, kB0 = (c0 & 3) * 8;
    int rowB1 = (c0 + 1) >> 2, kB1 = ((c0 + 1) & 3) * 8;
    const __half* bSrc0 = W + (long long)(n0 + rowB0) * ldw + kB0;
    const __half* bSrc1 = W + (long long)(n0 + rowB1) * ldw + kB1;
    unsigned bDst0 = (unsigned)__cvta_generic_to_shared(&Bs[0][rowB0 * HPAD + kB0]);
    unsigned bDst1 = (unsigned)__cvta_generic_to_shared(&Bs[0][rowB1 * HPAD + kB1]);

    int ntile = K / 32;
    float acc[2][4][4] = {};

#pragma unroll
    for (int s = 0; s < 2; s++) {
        cpa16(aDst  + s * H_AS * 2, aSrc  + s * 32);
        cpa16(bDst0 + s * H_BS * 2, bSrc0 + s * 32);
        cpa16(bDst1 + s * H_BS * 2, bSrc1 + s * 32);
        cpa_commit();
    }

    for (int it = 0; it < ntile; it++) {
        cpa_wait<1>();
        __syncthreads();
        if (it + 2 < ntile) {
            int s = (it + 2) % 3;
            int k0 = (it + 2) * 32;
            cpa16(aDst  + s * H_AS * 2, aSrc  + k0);
            cpa16(bDst0 + s * H_BS * 2, bSrc0 + k0);
            cpa16(bDst1 + s * H_BS * 2, bSrc1 + k0);
        }
        cpa_commit();
        const __half* Ab = As[it % 3];
        const __half* Bb = Bs[it % 3];
#pragma unroll
        for (int ks = 0; ks < 2; ks++) {
            int kb = ks * 16;
            unsigned a[2][4], b[4][2];
#pragma unroll
            for (int mt = 0; mt < 2; mt++) {
                const __half* base = &Ab[(wm + mt * 16 + g) * HPAD + kb + 2 * tg];
                a[mt][0] = *(const unsigned*)(base);
                a[mt][1] = *(const unsigned*)(base + 8 * HPAD);
                a[mt][2] = *(const unsigned*)(base + 8);
                a[mt][3] = *(const unsigned*)(base + 8 * HPAD + 8);
            }
#pragma unroll
            for (int nt = 0; nt < 4; nt++) {
                const __half* base = &Bb[(wn + nt * 8 + g) * HPAD + kb + 2 * tg];
                b[nt][0] = *(const unsigned*)(base);
                b[nt][1] = *(const unsigned*)(base + 8);
            }
#pragma unroll
            for (int mt = 0; mt < 2; mt++)
#pragma unroll
                for (int nt = 0; nt < 4; nt++)
                    mma16h(acc[mt][nt], a[mt], b[nt]);
        }
    }

    float* C32p = C32 ? C32 + blockIdx.z * cZ : (float*)0;
    __half* C16p = C16 ? C16 + blockIdx.z * cZ : (__half*)0;
#pragma unroll
    for (int mt = 0; mt < 2; mt++) {
#pragma unroll
        for (int nt = 0; nt < 4; nt++) {
            int col = n0 + wn + nt * 8 + 2 * tg;
            float b0 = 0.f, b1 = 0.f;
            if (Bias) { b0 = Bias[col]; b1 = Bias[col + 1]; }
            int row = m0 + wm + mt * 16 + g;
            float v00 = acc[mt][nt][0] * alpha + b0;
            float v01 = acc[mt][nt][1] * alpha + b1;
            float v10 = acc[mt][nt][2] * alpha + b0;
            float v11 = acc[mt][nt][3] * alpha + b1;
            if (relu) {
                v00 = fmaxf(v00, 0.f); v01 = fmaxf(v01, 0.f);
                v10 = fmaxf(v10, 0.f); v11 = fmaxf(v11, 0.f);
            }
            if (C32p) {
                *(float2*)&C32p[(long long)row * ldc + col] = make_float2(v00, v01);
                *(float2*)&C32p[(long long)(row + 8) * ldc + col] = make_float2(v10, v11);
            }
            if (C16p) {
                *(__half2*)&C16p[(long long)row * ldc + col] = __floats2half2_rn(v00, v01);
                *(__half2*)&C16p[(long long)(row + 8) * ldc + col] = __floats2half2_rn(v10, v11);
            }
        }
    }
}

// ============ NN GEMM (attn @ V): fp32 in, fp16 out. 64x64 tile. ============
#define SPAD 20
__global__ void __launch_bounds__(128) tf32_nn(
    const float* __restrict__ A, int lda, long long aZ,
    const float* __restrict__ B, int ldb, long long bZ,
    __half* __restrict__ C16, int ldc, long long cZ,
    int K)
{
    A += blockIdx.z * aZ; B += blockIdx.z * bZ; C16 += blockIdx.z * cZ;
    __shared__ unsigned As[2][64 * SPAD];
    __shared__ unsigned Bs[2][64 * SPAD];
    int tid = threadIdx.x;
    int warp = tid >> 5, lane = tid & 31;
    int g = lane >> 2, tg = lane & 3;
    int wm = (warp >> 1) * 32, wn = (warp & 1) * 32;
    int m0 = blockIdx.y * 64, n0 = blockIdx.x * 64;

    int lrow = tid >> 1;
    int lcol = (tid & 1) * 8;
    const float* Ap = A + (long long)(m0 + lrow) * lda + lcol;
    int sidx = lrow * SPAD + lcol;

    int f0 = tid * 2;
    int bk0 = f0 >> 4, bc0 = (f0 & 15) * 4;
    int bk1 = (f0 + 1) >> 4, bc1 = ((f0 + 1) & 15) * 4;
    const float* Bp0 = B + (long long)bk0 * ldb + n0 + bc0;
    const float* Bp1 = B + (long long)bk1 * ldb + n0 + bc1;

    float acc[2][4][4] = {};
    int ntile = K / 16;
    {
        float4 a0 = *(const float4*)(Ap);
        float4 a1 = *(const float4*)(Ap + 4);
        float4 v0 = *(const float4*)(Bp0);
        float4 v1 = *(const float4*)(Bp1);
        *(uint4*)&As[0][sidx]     = make_uint4(f2tf(a0.x), f2tf(a0.y), f2tf(a0.z), f2tf(a0.w));
        *(uint4*)&As[0][sidx + 4] = make_uint4(f2tf(a1.x), f2tf(a1.y), f2tf(a1.z), f2tf(a1.w));
        Bs[0][(bc0 + 0) * SPAD + bk0] = f2tf(v0.x);
        Bs[0][(bc0 + 1) * SPAD + bk0] = f2tf(v0.y);
        Bs[0][(bc0 + 2) * SPAD + bk0] = f2tf(v0.z);
        Bs[0][(bc0 + 3) * SPAD + bk0] = f2tf(v0.w);
        Bs[0][(bc1 + 0) * SPAD + bk1] = f2tf(v1.x);
        Bs[0][(bc1 + 1) * SPAD + bk1] = f2tf(v1.y);
        Bs[0][(bc1 + 2) * SPAD + bk1] = f2tf(v1.z);
        Bs[0][(bc1 + 3) * SPAD + bk1] = f2tf(v1.w);
    }
    __syncthreads();
    int p = 0;
    for (int it = 0; it < ntile; it++) {
        float4 na0, na1, nv0, nv1;
        if (it + 1 < ntile) {
            int ko = (it + 1) * 16;
            na0 = *(const float4*)(Ap + ko);
            na1 = *(const float4*)(Ap + ko + 4);
            nv0 = *(const float4*)(Bp0 + (long long)ko * ldb);
            nv1 = *(const float4*)(Bp1 + (long long)ko * ldb);
        }
#pragma unroll
        for (int ks = 0; ks < 2; ks++) {
            int kb = ks * 8;
            unsigned a[2][4], b[4][2];
#pragma unroll
            for (int mt = 0; mt < 2; mt++) {
                const unsigned* base = &As[p][(wm + mt * 16 + g) * SPAD + kb + tg];
                a[mt][0] = base[0];
                a[mt][1] = base[8 * SPAD];
                a[mt][2] = base[4];
                a[mt][3] = base[8 * SPAD + 4];
            }
#pragma unroll
            for (int nt = 0; nt < 4; nt++) {
                const unsigned* base = &Bs[p][(wn + nt * 8 + g) * SPAD + kb + tg];
                b[nt][0] = base[0];
                b[nt][1] = base[4];
            }
#pragma unroll
            for (int mt = 0; mt < 2; mt++)
#pragma unroll
                for (int nt = 0; nt < 4; nt++)
                    mma8(acc[mt][nt], a[mt], b[nt]);
        }
        if (it + 1 < ntile) {
            int q = p ^ 1;
            *(uint4*)&As[q][sidx]     = make_uint4(f2tf(na0.x), f2tf(na0.y), f2tf(na0.z), f2tf(na0.w));
            *(uint4*)&As[q][sidx + 4] = make_uint4(f2tf(na1.x), f2tf(na1.y), f2tf(na1.z), f2tf(na1.w));
            Bs[q][(bc0 + 0) * SPAD + bk0] = f2tf(nv0.x);
            Bs[q][(bc0 + 1) * SPAD + bk0] = f2tf(nv0.y);
            Bs[q][(bc0 + 2) * SPAD + bk0] = f2tf(nv0.z);
            Bs[q][(bc0 + 3) * SPAD + bk0] = f2tf(nv0.w);
            Bs[q][(bc1 + 0) * SPAD + bk1] = f2tf(nv1.x);
            Bs[q][(bc1 + 1) * SPAD + bk1] = f2tf(nv1.y);
            Bs[q][(bc1 + 2) * SPAD + bk1] = f2tf(nv1.z);
            Bs[q][(bc1 + 3) * SPAD + bk1] = f2tf(nv1.w);
        }
        __syncthreads();
        p ^= 1;
    }

#pragma unroll
    for (int mt = 0; mt < 2; mt++) {
#pragma unroll
        for (int nt = 0; nt < 4; nt++) {
            int col = n0 + wn + nt * 8 + 2 * tg;
            int row = m0 + wm + mt * 16 + g;
            *(__half2*)&C16[(long long)row * ldc + col] =
                __floats2half2_rn(acc[mt][nt][0], acc[mt][nt][1]);
            *(__half2*)&C16[(long long)(row + 8) * ldc + col] =
                __floats2half2_rn(acc[mt][nt][2], acc[mt][nt][3]);
        }
    }
}

// ---------------- row softmax (fp32) ----------------
__global__ void softmax_rows(float* __restrict__ S, int n) {
    float* row = S + (long long)blockIdx.x * n;
    __shared__ float red[128];
    int tid = threadIdx.x;
    float m = -1e30f;
    for (int j = tid; j < n; j += 128) m = fmaxf(m, row[j]);
    red[tid] = m; __syncthreads();
    for (int off = 64; off; off >>= 1) {
        if (tid < off) red[tid] = fmaxf(red[tid], red[tid + off]);
        __syncthreads();
    }
    m = red[0]; __syncthreads();
    float s = 0.f;
    for (int j = tid; j < n; j += 128) { float e = expf(row[j] - m); row[j] = e; s += e; }
    red[tid] = s; __syncthreads();
    for (int off = 64; off; off >>= 1) {
        if (tid < off) red[tid] += red[tid + off];
        __syncthreads();
    }
    float inv = 1.0f / red[0];
    for (int j = tid; j < n; j += 128) row[j] *= inv;
}

// ---------------- x = LN(x + delta); also writes fp16 shadow ----------------
__global__ void ln_res_kernel(float* __restrict__ x, __half* __restrict__ xh,
                              const float* __restrict__ delta,
                              const float* __restrict__ s, const float* __restrict__ b, int d) {
    float* xr = x + (long long)blockIdx.x * d;
    __half* xhr = xh + (long long)blockIdx.x * d;
    const float* dr = delta + (long long)blockIdx.x * d;
    __shared__ float red[256];
    int tid = threadIdx.x;
    float sum = 0.f;
    for (int j = tid; j < d; j += 256) { float v = xr[j] + dr[j]; xr[j] = v; sum += v; }
    red[tid] = sum; __syncthreads();
    for (int off = 128; off; off >>= 1) {
        if (tid < off) red[tid] += red[tid + off];
        __syncthreads();
    }
    float mean = red[0] / d; __syncthreads();
    float s2 = 0.f;
    for (int j = tid; j < d; j += 256) { float v = xr[j] - mean; s2 += v * v; }
    red[tid] = s2; __syncthreads();
    for (int off = 128; off; off >>= 1) {
        if (tid < off) red[tid] += red[tid + off];
        __syncthreads();
    }
    float inv = rsqrtf(red[0] / d + 1e-5f);
    __syncthreads();
    for (int j = tid; j < d; j += 256) {
        float v = (xr[j] - mean) * inv * s[j] + b[j];
        xr[j] = v;
        xhr[j] = __float2half(v);
    }
}

// ---------------- final linear ----------------
__global__ void lin_kernel(const float* __restrict__ x, const float* __restrict__ w,
                           const float* __restrict__ b, float* __restrict__ a,
                           float* __restrict__ c) {
    int i = blockIdx.x;
    const float* xr = x + (long long)i * CDIM;
    __shared__ float red[4][256];
    int tid = threadIdx.x;
    float s0 = 0, s1 = 0, s2 = 0, s3 = 0;
    for (int k = tid; k < CDIM; k += 256) {
        float xv = xr[k];
        s0 += xv * w[k];
        s1 += xv * w[2 * CDIM + k];
        s2 += xv * w[CDIM + k];
        s3 += xv * w[2 * CDIM + CDIM + k];
    }
    red[0][tid] = s0; red[1][tid] = s1; red[2][tid] = s2; red[3][tid] = s3;
    __syncthreads();
    for (int off = 128; off; off >>= 1) {
        if (tid < off) {
            red[0][tid] += red[0][tid + off];
            red[1][tid] += red[1][tid + off];
            red[2][tid] += red[2][tid + off];
            red[3][tid] += red[3][tid + off];
        }
        __syncthreads();
    }
    if (tid == 0) {
        a[2 * i]     = red[0][0] + b[0];
        a[2 * i + 1] = red[1][0] + b[1];
        c[2 * i]     = red[2][0];
        c[2 * i + 1] = red[3][0];
    }
}

// ---------------- pairwise probs + per-row loss partials ----------------
__global__ void pair_kernel(const float* __restrict__ a, const float* __restrict__ c,
                            const int* __restrict__ gt, float* __restrict__ probs,
                            float* __restrict__ rowcell, float* __restrict__ rowlink) {
    int i = blockIdx.x, j = threadIdx.x;
    float l0 = a[2 * i] + c[2 * j];
    float l1 = a[2 * i + 1] + c[2 * j + 1];
    float m = fmaxf(l0, l1);
    float e0 = expf(l0 - m), e1 = expf(l1 - m);
    float inv = 1.0f / (e0 + e1);
    float p0 = e0 * inv, p1 = e1 * inv;
    long long idx = ((long long)i * N_TOK + j) * 2;
    probs[idx] = p0; probs[idx + 1] = p1;
    float mm = fmaxf(p0, p1);
    float lse = mm + logf(expf(p0 - mm) + expf(p1 - mm));
    float pg = gt[i * N_TOK + j] ? p1 : p0;
    float cell = lse - pg;

    __shared__ float red[512];
    red[j] = cell;
    if (j < 128) red[384 + j] = 0.f;
    __syncthreads();
    for (int off = 256; off; off >>= 1) {
        if (j < off) red[j] += red[j + off];
        __syncthreads();
    }
    if (j == 0) rowcell[i] = red[0];
    __syncthreads();
    red[j] = p1;
    if (j < 128) red[384 + j] = 0.f;
    __syncthreads();
    for (int off = 256; off; off >>= 1) {
        if (j < off) red[j] += red[j + off];
        __syncthreads();
    }
    if (j == 0) rowlink[i] = red[0];
}

__global__ void col_kernel(const float* __restrict__ probs, float* __restrict__ collink) {
    int j = blockIdx.x; int tid = threadIdx.x;
    float s = 0.f;
    for (int i = tid; i < N_TOK; i += 128) s += probs[((long long)i * N_TOK + j) * 2 + 1];
    __shared__ float red[128];
    red[tid] = s; __syncthreads();
    for (int off = 64; off; off >>= 1) {
        if (tid < off) red[tid] += red[tid + off];
        __syncthreads();
    }
    if (tid == 0) collink[j] = red[0];
}

__global__ void final_kernel(const float* __restrict__ rowcell, const float* __restrict__ rowlink,
                             const float* __restrict__ collink, float* __restrict__ out,
                             int out_size) {
    __shared__ float r1[512], r2[512];
    int tid = threadIdx.x;
    r1[tid] = (tid < N_TOK) ? rowcell[tid] : 0.f;
    r2[tid] = (tid < N_TOK - 1) ? fabsf(rowlink[tid] + collink[tid] - 1.0f) : 0.f;
    __syncthreads();
    for (int off = 256; off; off >>= 1) {
        if (tid < off) { r1[tid] += r1[tid + off]; r2[tid] += r2[tid + off]; }
        __syncthreads();
    }
    if (tid == 0 && out_size >= N_TOK * N_TOK * 2 + 2) {
        out[N_TOK * N_TOK * 2]     = r1[0] / (float)N_TOK;
        out[N_TOK * N_TOK * 2 + 1] = r2[0];
    }
}

// ---------------- host orchestration ----------------
struct EncW {
    const __half *qkv_h, *out_h, *ff1_h, *ff2_h;       // converted weights
    const float *qkv_b, *out_b, *ln1_s, *ln1_b, *ff1_b, *ff2_b, *ln2_s, *ln2_b;
};

static void run_encoder(float* x, __half* xh, int d, const EncW& w,
                        float* qkv, __half* qkvh, float* sc, __half* oh,
                        float* y, __half* hh) {
    const int M = N_TOK;
    const int hd = d / NH;
    const float scale = 1.0f / sqrtf((float)hd);
    for (int l = 0; l < NLAYERS; l++) {
        // qkv = x @ Wq^T + Bq  (fp32 + fp16 outputs)
        h16_nt<<<dim3(3 * d / 128, M / 64, 1), 256>>>(
            xh, d, 0, w.qkv_h + (long long)l * 3 * d * d, d, 0,
            w.qkv_b + (long long)l * 3 * d, qkv, qkvh, 3 * d, 0, d, 1.f, 0);
        // scores[h] = Q_h @ K_h^T * scale
        h16_nt<<<dim3(M / 128, M / 64, NH), 256>>>(
            qkvh, 3 * d, hd, qkvh + d, 3 * d, hd, (const float*)0,
            sc, (__half*)0, M, (long long)M * M, hd, scale, 0);
        softmax_rows<<<NH * M, 128>>>(sc, M);
        // o = attn @ V (fp32 in, fp16 out)
        tf32_nn<<<dim3(hd / 64, M / 64, NH), 128>>>(
            sc, M, (long long)M * M, qkv + 2 * d, 3 * d, hd,
            oh, d, hd, M);
        // y = o @ out_w^T + out_b (fp32 out)
        h16_nt<<<dim3(d / 128, M / 64, 1), 256>>>(
            oh, d, 0, w.out_h + (long long)l * d * d, d, 0,
            w.out_b + (long long)l * d, y, (__half*)0, d, 0, d, 1.f, 0);
        ln_res_kernel<<<M, 256>>>(x, xh, y, w.ln1_s + (long long)l * d, w.ln1_b + (long long)l * d, d);
        // h = relu(x @ ff1^T + b1) (fp16 out only)
        h16_nt<<<dim3(FF_DIM / 128, M / 64, 1), 256>>>(
            xh, d, 0, w.ff1_h + (long long)l * FF_DIM * d, d, 0,
            w.ff1_b + (long long)l * FF_DIM, (float*)0, hh, FF_DIM, 0, d, 1.f, 1);
        // y = h @ ff2^T + b2 (fp32 out)
        h16_nt<<<dim3(d / 128, M / 64, 1), 256>>>(
            hh, FF_DIM, 0, w.ff2_h + (long long)l * d * FF_DIM, FF_DIM, 0,
            w.ff2_b + (long long)l * d, y, (__half*)0, d, 0, FF_DIM, 1.f, 0);
        ln_res_kernel<<<M, 256>>>(x, xh, y, w.ln2_s + (long long)l * d, w.ln2_b + (long long)l * d, d);
    }
}

extern "C" void kernel_launch(void* const* d_in, const int* in_sizes, int n_in,
                              void* d_out, int out_size) {
    const float* text   = (const float*)d_in[0];
    const float* vision = (const float*)d_in[1];
    const int*   gt     = (const int*)d_in[2];
    const float* lin_w  = (const float*)d_in[27];
    const float* lin_b  = (const float*)d_in[28];

    float* buf = nullptr;
    cudaGetSymbolAddress((void**)&buf, g_buf);
    __half* hb = nullptr;
    cudaGetSymbolAddress((void**)&hb, g_hbuf);

    float* x    = buf + OFF_X;
    float* x2   = buf + OFF_X2;
    float* qkv  = buf + OFF_QKV;
    float* sc   = buf + OFF_SC;
    float* y    = buf + OFF_Y;
    float* ga   = buf + OFF_A;
    float* gc   = buf + OFF_C;
    float* rcel = buf + OFF_RC;
    float* rlnk = buf + OFF_RL;
    float* clnk = buf + OFF_CL;

    __half* qkvh = hb + HA_QKV;
    __half* xh   = hb + HA_X;
    __half* oh   = hb + HA_O;
    __half* hh   = hb + HA_H;

    // ---- convert weights fp32 -> fp16 (once per launch) ----
    struct { long long off; int src; long long n; } cv[8] = {
        {HW_TQKV, 3,  3538944LL}, {HW_TOUT, 5,  1179648LL},
        {HW_TFF1, 9,  3145728LL}, {HW_TFF2, 11, 3145728LL},
        {HW_CQKV, 15, 14155776LL}, {HW_COUT, 17, 4718592LL},
        {HW_CFF1, 21, 6291456LL},  {HW_CFF2, 23, 6291456LL},
    };
    for (int i = 0; i < 8; i++) {
        int n4 = (int)(cv[i].n / 4);
        conv_k<<<(n4 + 255) / 256, 256>>>(hb + cv[i].off, (const float*)d_in[cv[i].src], n4);
    }

    EncW tw = {
        hb + HW_TQKV, hb + HW_TOUT, hb + HW_TFF1, hb + HW_TFF2,
        (const float*)d_in[4], (const float*)d_in[6],
        (const float*)d_in[7], (const float*)d_in[8],
        (const float*)d_in[10], (const float*)d_in[12],
        (const float*)d_in[13], (const float*)d_in[14]
    };
    EncW cw = {
        hb + HW_CQKV, hb + HW_COUT, hb + HW_CFF1, hb + HW_CFF2,
        (const float*)d_in[16], (const float*)d_in[18],
        (const float*)d_in[19], (const float*)d_in[20],
        (const float*)d_in[22], (const float*)d_in[24],
        (const float*)d_in[25], (const float*)d_in[26]
    };

    copy_k<<<(N_TOK * TDIM + 255) / 256, 256>>>(x, xh, text, N_TOK * TDIM);
    run_encoder(x, xh, TDIM, tw, qkv, qkvh, sc, oh, y, hh);

    concat_k<<<(N_TOK * CDIM + 255) / 256, 256>>>(x2, xh, x, vision);
    run_encoder(x2, xh, CDIM, cw, qkv, qkvh, sc, oh, y, hh);

    lin_kernel<<<N_TOK, 256>>>(x2, lin_w, lin_b, ga, gc);

    float* out = (float*)d_out;
    pair_kernel<<<N_TOK, N_TOK>>>(ga, gc, gt, out, rcel, rlnk);
    col_kernel<<<N_TOK, 128>>>(out, clnk);
    final_kernel<<<1, 512>>>(rcel, rlnk, clnk, out, out_size);
}

// round 8
// speedup vs baseline: 2.1404x; 1.1617x over previous
#include <cuda_runtime.h>
#include <cuda_fp16.h>
#include <math.h>
#include <stdint.h>

#define N_TOK 384
#define TDIM 768
#define VDIM 768
#define CDIM 1536
#define FF_DIM 2048
#define NH 4
#define NLAYERS 2

// ---------------- fp32 scratch ----------------
#define OFF_X   0LL
#define OFF_X2  589824LL
#define OFF_QKV 1179648LL
#define OFF_SC  2949120LL
#define OFF_Y   4128768LL
#define OFF_A   5505024LL
#define OFF_C   5505792LL
#define OFF_RC  5506560LL
#define OFF_RL  5506944LL
#define OFF_CL  5507328LL
#define BUF_TOTAL 5507712LL
__device__ float g_buf[BUF_TOTAL];

// ---------------- fp16 scratch ----------------
#define HW_TQKV 0LL
#define HW_TOUT 3538944LL
#define HW_TFF1 4718592LL
#define HW_TFF2 7864320LL
#define HW_CQKV 11010048LL
#define HW_COUT 25165824LL
#define HW_CFF1 29884416LL
#define HW_CFF2 36175872LL
#define HA_QKV  42467328LL
#define HA_X    44236800LL
#define HA_O    44826624LL
#define HA_H    45416448LL
#define HBUF_TOTAL 46202880LL
__device__ __half g_hbuf[HBUF_TOTAL];

// ---------------- helpers ----------------
__device__ __forceinline__ unsigned f2tf(float x) {
    unsigned u;
    asm("cvt.rna.tf32.f32 %0, %1;" : "=r"(u) : "f"(x));
    return u;
}
__device__ __forceinline__ void mma8(float* c, const unsigned* a, const unsigned* b) {
    asm volatile(
        "mma.sync.aligned.m16n8k8.row.col.f32.tf32.tf32.f32 "
        "{%0,%1,%2,%3},{%4,%5,%6,%7},{%8,%9},{%0,%1,%2,%3};"
        : "+f"(c[0]), "+f"(c[1]), "+f"(c[2]), "+f"(c[3])
        : "r"(a[0]), "r"(a[1]), "r"(a[2]), "r"(a[3]), "r"(b[0]), "r"(b[1]));
}
__device__ __forceinline__ void mma16h(float* c, const unsigned* a, const unsigned* b) {
    asm volatile(
        "mma.sync.aligned.m16n8k16.row.col.f32.f16.f16.f32 "
        "{%0,%1,%2,%3},{%4,%5,%6,%7},{%8,%9},{%0,%1,%2,%3};"
        : "+f"(c[0]), "+f"(c[1]), "+f"(c[2]), "+f"(c[3])
        : "r"(a[0]), "r"(a[1]), "r"(a[2]), "r"(a[3]), "r"(b[0]), "r"(b[1]));
}
__device__ __forceinline__ void cpa16(unsigned dst, const void* src) {
    asm volatile("cp.async.cg.shared.global [%0], [%1], 16;" :: "r"(dst), "l"(src));
}
__device__ __forceinline__ void cpa_commit() { asm volatile("cp.async.commit_group;"); }
template <int N>
__device__ __forceinline__ void cpa_wait() {
    asm volatile("cp.async.wait_group %0;" :: "n"(N));
}

// ---------------- merged weight conversion (8 segments, one launch) ----------------
struct ConvArgs {
    const float* src[8];
    long long dstOff[8];
    int cum[9];   // cumulative n4 boundaries
};
__global__ void conv_all(ConvArgs a, __half* __restrict__ hbase) {
    int i = blockIdx.x * blockDim.x + threadIdx.x;
    if (i >= a.cum[8]) return;
#pragma unroll
    for (int k = 0; k < 8; k++) {
        if (i < a.cum[k + 1]) {
            int local = i - a.cum[k];
            float4 v = ((const float4*)a.src[k])[local];
            __half2* d = (__half2*)(hbase + a.dstOff[k]) + local * 2;
            d[0] = __floats2half2_rn(v.x, v.y);
            d[1] = __floats2half2_rn(v.z, v.w);
            return;
        }
    }
}

__global__ void copy_k(float* __restrict__ dst, __half* __restrict__ dsth,
                       const float* __restrict__ src, int n) {
    int i = blockIdx.x * blockDim.x + threadIdx.x;
    if (i < n) { float v = src[i]; dst[i] = v; dsth[i] = __float2half(v); }
}
__global__ void concat_k(float* __restrict__ dst, __half* __restrict__ dsth,
                         const float* __restrict__ te, const float* __restrict__ vis) {
    int i = blockIdx.x * blockDim.x + threadIdx.x;
    if (i < N_TOK * CDIM) {
        int r = i / CDIM, c = i % CDIM;
        float v = (c < TDIM) ? te[r * TDIM + c] : vis[r * VDIM + (c - TDIM)];
        dst[i] = v; dsth[i] = __float2half(v);
    }
}

// ============ fp16 NT GEMM: C = alpha*A(MxK,row)@W(NxK,row)^T + bias ========
// 64x128 tile, BK=64 stages, 256 threads = 8 warps (2x4), warp tile 32x32.
// 3-stage cp.async ring in dynamic smem. HPAD=72 halves (144B rows).
#define HPAD 72
#define A_BYTES (64 * HPAD * 2)     // 9216
#define B_BYTES (128 * HPAD * 2)    // 18432
#define STG (A_BYTES + B_BYTES)     // 27648
#define H_SMEM (3 * STG)            // 82944

__global__ void __launch_bounds__(256) h16_nt(
    const __half* __restrict__ A, int lda, long long aZ,
    const __half* __restrict__ W, int ldw, long long wZ,
    const float* __restrict__ Bias,
    float* __restrict__ C32, __half* __restrict__ C16,
    int ldc, long long cZ,
    int K, float alpha, int relu)
{
    extern __shared__ __half hsm[];
    uint32_t base = (uint32_t)__cvta_generic_to_shared(hsm);
    A += blockIdx.z * aZ; W += blockIdx.z * wZ;

    int tid = threadIdx.x;
    int warp = tid >> 5, lane = tid & 31;
    int g = lane >> 2, tg = lane & 3;
    int wm = (warp >> 2) * 32, wn = (warp & 3) * 32;
    int m0 = blockIdx.y * 64, n0 = blockIdx.x * 128;

    int S = K / 64;
    float acc[2][4][4] = {};

    auto loadStage = [&](int s) {
        uint32_t st = base + (uint32_t)(s % 3) * STG;
        const __half* Ak = A + (long long)s * 64;
        const __half* Wk = W + (long long)s * 64;
#pragma unroll
        for (int j = 0; j < 2; j++) {
            int c = tid + j * 256;
            int r = c >> 3, kq = (c & 7) * 8;
            cpa16(st + (uint32_t)r * 144u + (uint32_t)kq * 2u,
                  Ak + (long long)(m0 + r) * lda + kq);
        }
        uint32_t bs = st + A_BYTES;
#pragma unroll
        for (int j = 0; j < 4; j++) {
            int c = tid + j * 256;
            int r = c >> 3, kq = (c & 7) * 8;
            cpa16(bs + (uint32_t)r * 144u + (uint32_t)kq * 2u,
                  Wk + (long long)(n0 + r) * ldw + kq);
        }
        cpa_commit();
    };

    loadStage(0);
    loadStage(1);

    for (int s = 0; s < S; s++) {
        if (s == S - 1) cpa_wait<0>(); else cpa_wait<1>();
        __syncthreads();
        if (s + 2 < S) loadStage(s + 2);
        else cpa_commit();   // keep group count consistent for waits

        const __half* Ab = hsm + (long long)(s % 3) * (STG / 2);
        const __half* Bb = Ab + A_BYTES / 2;
#pragma unroll
        for (int ks = 0; ks < 4; ks++) {
            int kb = ks * 16;
            unsigned a[2][4], b[4][2];
#pragma unroll
            for (int mt = 0; mt < 2; mt++) {
                const __half* p = &Ab[(wm + mt * 16 + g) * HPAD + kb + 2 * tg];
                a[mt][0] = *(const unsigned*)(p);
                a[mt][1] = *(const unsigned*)(p + 8 * HPAD);
                a[mt][2] = *(const unsigned*)(p + 8);
                a[mt][3] = *(const unsigned*)(p + 8 * HPAD + 8);
            }
#pragma unroll
            for (int nt = 0; nt < 4; nt++) {
                const __half* p = &Bb[(wn + nt * 8 + g) * HPAD + kb + 2 * tg];
                b[nt][0] = *(const unsigned*)(p);
                b[nt][1] = *(const unsigned*)(p + 8);
            }
#pragma unroll
            for (int mt = 0; mt < 2; mt++)
#pragma unroll
                for (int nt = 0; nt < 4; nt++)
                    mma16h(acc[mt][nt], a[mt], b[nt]);
        }
        __syncthreads();
    }

    float* C32p = C32 ? C32 + blockIdx.z * cZ : (float*)0;
    __half* C16p = C16 ? C16 + blockIdx.z * cZ : (__half*)0;
#pragma unroll
    for (int mt = 0; mt < 2; mt++) {
#pragma unroll
        for (int nt = 0; nt < 4; nt++) {
            int col = n0 + wn + nt * 8 + 2 * tg;
            float b0 = 0.f, b1 = 0.f;
            if (Bias) { b0 = Bias[col]; b1 = Bias[col + 1]; }
            int row = m0 + wm + mt * 16 + g;
            float v00 = acc[mt][nt][0] * alpha + b0;
            float v01 = acc[mt][nt][1] * alpha + b1;
            float v10 = acc[mt][nt][2] * alpha + b0;
            float v11 = acc[mt][nt][3] * alpha + b1;
            if (relu) {
                v00 = fmaxf(v00, 0.f); v01 = fmaxf(v01, 0.f);
                v10 = fmaxf(v10, 0.f); v11 = fmaxf(v11, 0.f);
            }
            if (C32p) {
                *(float2*)&C32p[(long long)row * ldc + col] = make_float2(v00, v01);
                *(float2*)&C32p[(long long)(row + 8) * ldc + col] = make_float2(v10, v11);
            }
            if (C16p) {
                *(__half2*)&C16p[(long long)row * ldc + col] = __floats2half2_rn(v00, v01);
                *(__half2*)&C16p[(long long)(row + 8) * ldc + col] = __floats2half2_rn(v10, v11);
            }
        }
    }
}

// ============ NN GEMM (attn @ V): fp32 in, fp16 out. 64x64 tile. ============
#define SPAD 20
__global__ void __launch_bounds__(128) tf32_nn(
    const float* __restrict__ A, int lda, long long aZ,
    const float* __restrict__ B, int ldb, long long bZ,
    __half* __restrict__ C16, int ldc, long long cZ,
    int K)
{
    A += blockIdx.z * aZ; B += blockIdx.z * bZ; C16 += blockIdx.z * cZ;
    __shared__ unsigned As[2][64 * SPAD];
    __shared__ unsigned Bs[2][64 * SPAD];
    int tid = threadIdx.x;
    int warp = tid >> 5, lane = tid & 31;
    int g = lane >> 2, tg = lane & 3;
    int wm = (warp >> 1) * 32, wn = (warp & 1) * 32;
    int m0 = blockIdx.y * 64, n0 = blockIdx.x * 64;

    int lrow = tid >> 1;
    int lcol = (tid & 1) * 8;
    const float* Ap = A + (long long)(m0 + lrow) * lda + lcol;
    int sidx = lrow * SPAD + lcol;

    int f0 = tid * 2;
    int bk0 = f0 >> 4, bc0 = (f0 & 15) * 4;
    int bk1 = (f0 + 1) >> 4, bc1 = ((f0 + 1) & 15) * 4;
    const float* Bp0 = B + (long long)bk0 * ldb + n0 + bc0;
    const float* Bp1 = B + (long long)bk1 * ldb + n0 + bc1;

    float acc[2][4][4] = {};
    int ntile = K / 16;
    {
        float4 a0 = *(const float4*)(Ap);
        float4 a1 = *(const float4*)(Ap + 4);
        float4 v0 = *(const float4*)(Bp0);
        float4 v1 = *(const float4*)(Bp1);
        *(uint4*)&As[0][sidx]     = make_uint4(f2tf(a0.x), f2tf(a0.y), f2tf(a0.z), f2tf(a0.w));
        *(uint4*)&As[0][sidx + 4] = make_uint4(f2tf(a1.x), f2tf(a1.y), f2tf(a1.z), f2tf(a1.w));
        Bs[0][(bc0 + 0) * SPAD + bk0] = f2tf(v0.x);
        Bs[0][(bc0 + 1) * SPAD + bk0] = f2tf(v0.y);
        Bs[0][(bc0 + 2) * SPAD + bk0] = f2tf(v0.z);
        Bs[0][(bc0 + 3) * SPAD + bk0] = f2tf(v0.w);
        Bs[0][(bc1 + 0) * SPAD + bk1] = f2tf(v1.x);
        Bs[0][(bc1 + 1) * SPAD + bk1] = f2tf(v1.y);
        Bs[0][(bc1 + 2) * SPAD + bk1] = f2tf(v1.z);
        Bs[0][(bc1 + 3) * SPAD + bk1] = f2tf(v1.w);
    }
    __syncthreads();
    int p = 0;
    for (int it = 0; it < ntile; it++) {
        float4 na0, na1, nv0, nv1;
        if (it + 1 < ntile) {
            int ko = (it + 1) * 16;
            na0 = *(const float4*)(Ap + ko);
            na1 = *(const float4*)(Ap + ko + 4);
            nv0 = *(const float4*)(Bp0 + (long long)ko * ldb);
            nv1 = *(const float4*)(Bp1 + (long long)ko * ldb);
        }
#pragma unroll
        for (int ks = 0; ks < 2; ks++) {
            int kb = ks * 8;
            unsigned a[2][4], b[4][2];
#pragma unroll
            for (int mt = 0; mt < 2; mt++) {
                const unsigned* base2 = &As[p][(wm + mt * 16 + g) * SPAD + kb + tg];
                a[mt][0] = base2[0];
                a[mt][1] = base2[8 * SPAD];
                a[mt][2] = base2[4];
                a[mt][3] = base2[8 * SPAD + 4];
            }
#pragma unroll
            for (int nt = 0; nt < 4; nt++) {
                const unsigned* base2 = &Bs[p][(wn + nt * 8 + g) * SPAD + kb + tg];
                b[nt][0] = base2[0];
                b[nt][1] = base2[4];
            }
#pragma unroll
            for (int mt = 0; mt < 2; mt++)
#pragma unroll
                for (int nt = 0; nt < 4; nt++)
                    mma8(acc[mt][nt], a[mt], b[nt]);
        }
        if (it + 1 < ntile) {
            int q = p ^ 1;
            *(uint4*)&As[q][sidx]     = make_uint4(f2tf(na0.x), f2tf(na0.y), f2tf(na0.z), f2tf(na0.w));
            *(uint4*)&As[q][sidx + 4] = make_uint4(f2tf(na1.x), f2tf(na1.y), f2tf(na1.z), f2tf(na1.w));
            Bs[q][(bc0 + 0) * SPAD + bk0] = f2tf(nv0.x);
            Bs[q][(bc0 + 1) * SPAD + bk0] = f2tf(nv0.y);
            Bs[q][(bc0 + 2) * SPAD + bk0] = f2tf(nv0.z);
            Bs[q][(bc0 + 3) * SPAD + bk0] = f2tf(nv0.w);
            Bs[q][(bc1 + 0) * SPAD + bk1] = f2tf(nv1.x);
            Bs[q][(bc1 + 1) * SPAD + bk1] = f2tf(nv1.y);
            Bs[q][(bc1 + 2) * SPAD + bk1] = f2tf(nv1.z);
            Bs[q][(bc1 + 3) * SPAD + bk1] = f2tf(nv1.w);
        }
        __syncthreads();
        p ^= 1;
    }

#pragma unroll
    for (int mt = 0; mt < 2; mt++) {
#pragma unroll
        for (int nt = 0; nt < 4; nt++) {
            int col = n0 + wn + nt * 8 + 2 * tg;
            int row = m0 + wm + mt * 16 + g;
            *(__half2*)&C16[(long long)row * ldc + col] =
                __floats2half2_rn(acc[mt][nt][0], acc[mt][nt][1]);
            *(__half2*)&C16[(long long)(row + 8) * ldc + col] =
                __floats2half2_rn(acc[mt][nt][2], acc[mt][nt][3]);
        }
    }
}

// ---------------- row softmax (fp32) ----------------
__global__ void softmax_rows(float* __restrict__ S, int n) {
    float* row = S + (long long)blockIdx.x * n;
    __shared__ float red[128];
    int tid = threadIdx.x;
    float m = -1e30f;
    for (int j = tid; j < n; j += 128) m = fmaxf(m, row[j]);
    red[tid] = m; __syncthreads();
    for (int off = 64; off; off >>= 1) {
        if (tid < off) red[tid] = fmaxf(red[tid], red[tid + off]);
        __syncthreads();
    }
    m = red[0]; __syncthreads();
    float s = 0.f;
    for (int j = tid; j < n; j += 128) { float e = expf(row[j] - m); row[j] = e; s += e; }
    red[tid] = s; __syncthreads();
    for (int off = 64; off; off >>= 1) {
        if (tid < off) red[tid] += red[tid + off];
        __syncthreads();
    }
    float inv = 1.0f / red[0];
    for (int j = tid; j < n; j += 128) row[j] *= inv;
}

// ---------------- x = LN(x + delta); fp16 shadow ----------------
__global__ void ln_res_kernel(float* __restrict__ x, __half* __restrict__ xh,
                              const float* __restrict__ delta,
                              const float* __restrict__ s, const float* __restrict__ b, int d) {
    float* xr = x + (long long)blockIdx.x * d;
    __half* xhr = xh + (long long)blockIdx.x * d;
    const float* dr = delta + (long long)blockIdx.x * d;
    __shared__ float red[256];
    int tid = threadIdx.x;
    float sum = 0.f;
    for (int j = tid; j < d; j += 256) { float v = xr[j] + dr[j]; xr[j] = v; sum += v; }
    red[tid] = sum; __syncthreads();
    for (int off = 128; off; off >>= 1) {
        if (tid < off) red[tid] += red[tid + off];
        __syncthreads();
    }
    float mean = red[0] / d; __syncthreads();
    float s2 = 0.f;
    for (int j = tid; j < d; j += 256) { float v = xr[j] - mean; s2 += v * v; }
    red[tid] = s2; __syncthreads();
    for (int off = 128; off; off >>= 1) {
        if (tid < off) red[tid] += red[tid + off];
        __syncthreads();
    }
    float inv = rsqrtf(red[0] / d + 1e-5f);
    __syncthreads();
    for (int j = tid; j < d; j += 256) {
        float v = (xr[j] - mean) * inv * s[j] + b[j];
        xr[j] = v;
        xhr[j] = __float2half(v);
    }
}

// ---------------- final linear ----------------
__global__ void lin_kernel(const float* __restrict__ x, const float* __restrict__ w,
                           const float* __restrict__ b, float* __restrict__ a,
                           float* __restrict__ c) {
    int i = blockIdx.x;
    const float* xr = x + (long long)i * CDIM;
    __shared__ float red[4][256];
    int tid = threadIdx.x;
    float s0 = 0, s1 = 0, s2 = 0, s3 = 0;
    for (int k = tid; k < CDIM; k += 256) {
        float xv = xr[k];
        s0 += xv * w[k];
        s1 += xv * w[2 * CDIM + k];
        s2 += xv * w[CDIM + k];
        s3 += xv * w[2 * CDIM + CDIM + k];
    }
    red[0][tid] = s0; red[1][tid] = s1; red[2][tid] = s2; red[3][tid] = s3;
    __syncthreads();
    for (int off = 128; off; off >>= 1) {
        if (tid < off) {
            red[0][tid] += red[0][tid + off];
            red[1][tid] += red[1][tid + off];
            red[2][tid] += red[2][tid + off];
            red[3][tid] += red[3][tid + off];
        }
        __syncthreads();
    }
    if (tid == 0) {
        a[2 * i]     = red[0][0] + b[0];
        a[2 * i + 1] = red[1][0] + b[1];
        c[2 * i]     = red[2][0];
        c[2 * i + 1] = red[3][0];
    }
}

// ---------------- pairwise probs + loss partials ----------------
__global__ void pair_kernel(const float* __restrict__ a, const float* __restrict__ c,
                            const int* __restrict__ gt, float* __restrict__ probs,
                            float* __restrict__ rowcell, float* __restrict__ rowlink) {
    int i = blockIdx.x, j = threadIdx.x;
    float l0 = a[2 * i] + c[2 * j];
    float l1 = a[2 * i + 1] + c[2 * j + 1];
    float m = fmaxf(l0, l1);
    float e0 = expf(l0 - m), e1 = expf(l1 - m);
    float inv = 1.0f / (e0 + e1);
    float p0 = e0 * inv, p1 = e1 * inv;
    long long idx = ((long long)i * N_TOK + j) * 2;
    probs[idx] = p0; probs[idx + 1] = p1;
    float mm = fmaxf(p0, p1);
    float lse = mm + logf(expf(p0 - mm) + expf(p1 - mm));
    float pg = gt[i * N_TOK + j] ? p1 : p0;
    float cell = lse - pg;

    __shared__ float red[512];
    red[j] = cell;
    if (j < 128) red[384 + j] = 0.f;
    __syncthreads();
    for (int off = 256; off; off >>= 1) {
        if (j < off) red[j] += red[j + off];
        __syncthreads();
    }
    if (j == 0) rowcell[i] = red[0];
    __syncthreads();
    red[j] = p1;
    if (j < 128) red[384 + j] = 0.f;
    __syncthreads();
    for (int off = 256; off; off >>= 1) {
        if (j < off) red[j] += red[j + off];
        __syncthreads();
    }
    if (j == 0) rowlink[i] = red[0];
}

__global__ void col_kernel(const float* __restrict__ probs, float* __restrict__ collink) {
    int j = blockIdx.x; int tid = threadIdx.x;
    float s = 0.f;
    for (int i = tid; i < N_TOK; i += 128) s += probs[((long long)i * N_TOK + j) * 2 + 1];
    __shared__ float red[128];
    red[tid] = s; __syncthreads();
    for (int off = 64; off; off >>= 1) {
        if (tid < off) red[tid] += red[tid + off];
        __syncthreads();
    }
    if (tid == 0) collink[j] = red[0];
}

__global__ void final_kernel(const float* __restrict__ rowcell, const float* __restrict__ rowlink,
                             const float* __restrict__ collink, float* __restrict__ out,
                             int out_size) {
    __shared__ float r1[512], r2[512];
    int tid = threadIdx.x;
    r1[tid] = (tid < N_TOK) ? rowcell[tid] : 0.f;
    r2[tid] = (tid < N_TOK - 1) ? fabsf(rowlink[tid] + collink[tid] - 1.0f) : 0.f;
    __syncthreads();
    for (int off = 256; off; off >>= 1) {
        if (tid < off) { r1[tid] += r1[tid + off]; r2[tid] += r2[tid + off]; }
        __syncthreads();
    }
    if (tid == 0 && out_size >= N_TOK * N_TOK * 2 + 2) {
        out[N_TOK * N_TOK * 2]     = r1[0] / (float)N_TOK;
        out[N_TOK * N_TOK * 2 + 1] = r2[0];
    }
}

// ---------------- host orchestration ----------------
struct EncW {
    const __half *qkv_h, *out_h, *ff1_h, *ff2_h;
    const float *qkv_b, *out_b, *ln1_s, *ln1_b, *ff1_b, *ff2_b, *ln2_s, *ln2_b;
};

static void run_encoder(float* x, __half* xh, int d, const EncW& w,
                        float* qkv, __half* qkvh, float* sc, __half* oh,
                        float* y, __half* hh) {
    const int M = N_TOK;
    const int hd = d / NH;
    const float scale = 1.0f / sqrtf((float)hd);
    for (int l = 0; l < NLAYERS; l++) {
        // qkv = x @ Wq^T + Bq (fp32 + fp16 out)
        h16_nt<<<dim3(3 * d / 128, M / 64, 1), 256, H_SMEM>>>(
            xh, d, 0, w.qkv_h + (long long)l * 3 * d * d, d, 0,
            w.qkv_b + (long long)l * 3 * d, qkv, qkvh, 3 * d, 0, d, 1.f, 0);
        // scores[h] = Q_h @ K_h^T * scale (fp32 out)
        h16_nt<<<dim3(M / 128, M / 64, NH), 256, H_SMEM>>>(
            qkvh, 3 * d, hd, qkvh + d, 3 * d, hd, (const float*)0,
            sc, (__half*)0, M, (long long)M * M, hd, scale, 0);
        softmax_rows<<<NH * M, 128>>>(sc, M);
        // o = attn @ V (fp32 in, fp16 out)
        tf32_nn<<<dim3(hd / 64, M / 64, NH), 128>>>(
            sc, M, (long long)M * M, qkv + 2 * d, 3 * d, hd,
            oh, d, hd, M);
        // y = o @ out_w^T + out_b (fp32 out)
        h16_nt<<<dim3(d / 128, M / 64, 1), 256, H_SMEM>>>(
            oh, d, 0, w.out_h + (long long)l * d * d, d, 0,
            w.out_b + (long long)l * d, y, (__half*)0, d, 0, d, 1.f, 0);
        ln_res_kernel<<<M, 256>>>(x, xh, y, w.ln1_s + (long long)l * d, w.ln1_b + (long long)l * d, d);
        // h = relu(x @ ff1^T + b1) (fp16 out)
        h16_nt<<<dim3(FF_DIM / 128, M / 64, 1), 256, H_SMEM>>>(
            xh, d, 0, w.ff1_h + (long long)l * FF_DIM * d, d, 0,
            w.ff1_b + (long long)l * FF_DIM, (float*)0, hh, FF_DIM, 0, d, 1.f, 1);
        // y = h @ ff2^T + b2 (fp32 out)
        h16_nt<<<dim3(d / 128, M / 64, 1), 256, H_SMEM>>>(
            hh, FF_DIM, 0, w.ff2_h + (long long)l * d * FF_DIM, FF_DIM, 0,
            w.ff2_b + (long long)l * d, y, (__half*)0, d, 0, FF_DIM, 1.f, 0);
        ln_res_kernel<<<M, 256>>>(x, xh, y, w.ln2_s + (long long)l * d, w.ln2_b + (long long)l * d, d);
    }
}

extern "C" void kernel_launch(void* const* d_in, const int* in_sizes, int n_in,
                              void* d_out, int out_size) {
    const float* text   = (const float*)d_in[0];
    const float* vision = (const float*)d_in[1];
    const int*   gt     = (const int*)d_in[2];
    const float* lin_w  = (const float*)d_in[27];
    const float* lin_b  = (const float*)d_in[28];

    static int inited = 0;
    if (!inited) {
        cudaFuncSetAttribute(h16_nt, cudaFuncAttributeMaxDynamicSharedMemorySize, H_SMEM);
        inited = 1;
    }

    float* buf = nullptr;
    cudaGetSymbolAddress((void**)&buf, g_buf);
    __half* hb = nullptr;
    cudaGetSymbolAddress((void**)&hb, g_hbuf);

    float* x    = buf + OFF_X;
    float* x2   = buf + OFF_X2;
    float* qkv  = buf + OFF_QKV;
    float* sc   = buf + OFF_SC;
    float* y    = buf + OFF_Y;
    float* ga   = buf + OFF_A;
    float* gc   = buf + OFF_C;
    float* rcel = buf + OFF_RC;
    float* rlnk = buf + OFF_RL;
    float* clnk = buf + OFF_CL;

    __half* qkvh = hb + HA_QKV;
    __half* xh   = hb + HA_X;
    __half* oh   = hb + HA_O;
    __half* hh   = hb + HA_H;

    // ---- merged weight conversion (one launch for all 8 weight tensors) ----
    ConvArgs ca;
    const long long offs[8] = {HW_TQKV, HW_TOUT, HW_TFF1, HW_TFF2,
                               HW_CQKV, HW_COUT, HW_CFF1, HW_CFF2};
    const int srcs[8] = {3, 5, 9, 11, 15, 17, 21, 23};
    const long long ns[8] = {3538944LL, 1179648LL, 3145728LL, 3145728LL,
                             14155776LL, 4718592LL, 6291456LL, 6291456LL};
    ca.cum[0] = 0;
    for (int i = 0; i < 8; i++) {
        ca.src[i] = (const float*)d_in[srcs[i]];
        ca.dstOff[i] = offs[i];
        ca.cum[i + 1] = ca.cum[i] + (int)(ns[i] / 4);
    }
    conv_all<<<(ca.cum[8] + 255) / 256, 256>>>(ca, hb);

    EncW tw = {
        hb + HW_TQKV, hb + HW_TOUT, hb + HW_TFF1, hb + HW_TFF2,
        (const float*)d_in[4], (const float*)d_in[6],
        (const float*)d_in[7], (const float*)d_in[8],
        (const float*)d_in[10], (const float*)d_in[12],
        (const float*)d_in[13], (const float*)d_in[14]
    };
    EncW cw = {
        hb + HW_CQKV, hb + HW_COUT, hb + HW_CFF1, hb + HW_CFF2,
        (const float*)d_in[16], (const float*)d_in[18],
        (const float*)d_in[19], (const float*)d_in[20],
        (const float*)d_in[22], (const float*)d_in[24],
        (const float*)d_in[25], (const float*)d_in[26]
    };

    copy_k<<<(N_TOK * TDIM + 255) / 256, 256>>>(x, xh, text, N_TOK * TDIM);
    run_encoder(x, xh, TDIM, tw, qkv, qkvh, sc, oh, y, hh);

    concat_k<<<(N_TOK * CDIM + 255) / 256, 256>>>(x2, xh, x, vision);
    run_encoder(x2, xh, CDIM, cw, qkv, qkvh, sc, oh, y, hh);

    lin_kernel<<<N_TOK, 256>>>(x2, lin_w, lin_b, ga, gc);

    float* out = (float*)d_out;
    pair_kernel<<<N_TOK, N_TOK>>>(ga, gc, gt, out, rcel, rlnk);
    col_kernel<<<N_TOK, 128>>>(out, clnk);
    final_kernel<<<1, 512>>>(rcel, rlnk, clnk, out, out_size);
}

// round 9
// speedup vs baseline: 2.2109x; 1.0329x over previous
#include <cuda_runtime.h>
#include <cuda_fp16.h>
#include <math.h>
#include <stdint.h>

#define N_TOK 384
#define TDIM 768
#define VDIM 768
#define CDIM 1536
#define FF_DIM 2048
#define NH 4
#define NLAYERS 2

// ---------------- fp32 scratch ----------------
#define OFF_X   0LL
#define OFF_X2  589824LL
#define OFF_QKV 1179648LL
#define OFF_SC  2949120LL
#define OFF_Y   4128768LL
#define OFF_A   5505024LL
#define OFF_C   5505792LL
#define OFF_RC  5506560LL
#define OFF_RL  5506944LL
#define OFF_CL  5507328LL
#define BUF_TOTAL 5507712LL
__device__ float g_buf[BUF_TOTAL];

// ---------------- fp16 scratch ----------------
#define HW_TQKV 0LL
#define HW_TOUT 3538944LL
#define HW_TFF1 4718592LL
#define HW_TFF2 7864320LL
#define HW_CQKV 11010048LL
#define HW_COUT 25165824LL
#define HW_CFF1 29884416LL
#define HW_CFF2 36175872LL
#define HA_QKV  42467328LL
#define HA_X    44236800LL
#define HA_O    44826624LL
#define HA_H    45416448LL
#define HBUF_TOTAL 46202880LL
__device__ __half g_hbuf[HBUF_TOTAL];

// ---------------- helpers ----------------
__device__ __forceinline__ unsigned f2tf(float x) {
    unsigned u;
    asm("cvt.rna.tf32.f32 %0, %1;" : "=r"(u) : "f"(x));
    return u;
}
__device__ __forceinline__ void mma8(float* c, const unsigned* a, const unsigned* b) {
    asm volatile(
        "mma.sync.aligned.m16n8k8.row.col.f32.tf32.tf32.f32 "
        "{%0,%1,%2,%3},{%4,%5,%6,%7},{%8,%9},{%0,%1,%2,%3};"
        : "+f"(c[0]), "+f"(c[1]), "+f"(c[2]), "+f"(c[3])
        : "r"(a[0]), "r"(a[1]), "r"(a[2]), "r"(a[3]), "r"(b[0]), "r"(b[1]));
}
__device__ __forceinline__ void mma16h(float* c, const unsigned* a, const unsigned* b) {
    asm volatile(
        "mma.sync.aligned.m16n8k16.row.col.f32.f16.f16.f32 "
        "{%0,%1,%2,%3},{%4,%5,%6,%7},{%8,%9},{%0,%1,%2,%3};"
        : "+f"(c[0]), "+f"(c[1]), "+f"(c[2]), "+f"(c[3])
        : "r"(a[0]), "r"(a[1]), "r"(a[2]), "r"(a[3]), "r"(b[0]), "r"(b[1]));
}
__device__ __forceinline__ void ldsm_x4(unsigned* r, uint32_t addr) {
    asm volatile("ldmatrix.sync.aligned.m8n8.x4.shared.b16 {%0,%1,%2,%3}, [%4];"
        : "=r"(r[0]), "=r"(r[1]), "=r"(r[2]), "=r"(r[3]) : "r"(addr));
}
__device__ __forceinline__ void cpa16(unsigned dst, const void* src) {
    asm volatile("cp.async.cg.shared.global [%0], [%1], 16;" :: "r"(dst), "l"(src));
}
__device__ __forceinline__ void cpa_commit() { asm volatile("cp.async.commit_group;"); }
template <int N>
__device__ __forceinline__ void cpa_wait() {
    asm volatile("cp.async.wait_group %0;" :: "n"(N));
}

// ---------------- merged weight conversion ----------------
struct ConvArgs {
    const float* src[8];
    long long dstOff[8];
    int cum[9];
};
__global__ void conv_all(ConvArgs a, __half* __restrict__ hbase) {
    int i = blockIdx.x * blockDim.x + threadIdx.x;
    if (i >= a.cum[8]) return;
#pragma unroll
    for (int k = 0; k < 8; k++) {
        if (i < a.cum[k + 1]) {
            int local = i - a.cum[k];
            float4 v = ((const float4*)a.src[k])[local];
            __half2* d = (__half2*)(hbase + a.dstOff[k]) + local * 2;
            d[0] = __floats2half2_rn(v.x, v.y);
            d[1] = __floats2half2_rn(v.z, v.w);
            return;
        }
    }
}

__global__ void copy_k(float* __restrict__ dst, __half* __restrict__ dsth,
                       const float* __restrict__ src, int n) {
    int i = blockIdx.x * blockDim.x + threadIdx.x;
    if (i < n) { float v = src[i]; dst[i] = v; dsth[i] = __float2half(v); }
}
__global__ void concat_k(float* __restrict__ dst, __half* __restrict__ dsth,
                         const float* __restrict__ te, const float* __restrict__ vis) {
    int i = blockIdx.x * blockDim.x + threadIdx.x;
    if (i < N_TOK * CDIM) {
        int r = i / CDIM, c = i % CDIM;
        float v = (c < TDIM) ? te[r * TDIM + c] : vis[r * VDIM + (c - TDIM)];
        dst[i] = v; dsth[i] = __float2half(v);
    }
}

// ============ fp16 NT GEMM: C = alpha*A(MxK,row)@W(NxK,row)^T + bias ========
// 64x128 tile, BK=64 stages, 256 threads = 8 warps (2x4), warp tile 32x32.
// 3-stage cp.async ring; ldmatrix.x4 fragment loads double-buffered across ks.
#define HPAD 72
#define A_BYTES (64 * HPAD * 2)     // 9216
#define B_BYTES (128 * HPAD * 2)    // 18432
#define STG (A_BYTES + B_BYTES)     // 27648
#define H_SMEM (3 * STG)            // 82944

__global__ void __launch_bounds__(256) h16_nt(
    const __half* __restrict__ A, int lda, long long aZ,
    const __half* __restrict__ W, int ldw, long long wZ,
    const float* __restrict__ Bias,
    float* __restrict__ C32, __half* __restrict__ C16,
    int ldc, long long cZ,
    int K, float alpha, int relu)
{
    extern __shared__ __half hsm[];
    uint32_t base = (uint32_t)__cvta_generic_to_shared(hsm);
    A += blockIdx.z * aZ; W += blockIdx.z * wZ;

    int tid = threadIdx.x;
    int warp = tid >> 5, lane = tid & 31;
    int g = lane >> 2, tg = lane & 3;
    int wm = (warp >> 2) * 32, wn = (warp & 3) * 32;
    int m0 = blockIdx.y * 64, n0 = blockIdx.x * 128;

    int S = K / 64;
    float acc[2][4][4] = {};

    // ldmatrix lane-address components
    // A x4 (per mt): matrices (m-lo,k-lo),(m-hi,k-lo),(m-lo,k-hi),(m-hi,k-hi)
    int aRow = (lane & 7) + ((lane >> 3) & 1) * 8;   // within 16-row tile
    int aK   = ((lane >> 4) & 1) * 8;                // k-half
    // B x4 (per nt-pair): matrices (nt,k-lo),(nt,k-hi),(nt+1,k-lo),(nt+1,k-hi)
    int bRow = ((lane >> 4) & 1) * 8 + (lane & 7);   // within 16-n-row pair
    int bK   = ((lane >> 3) & 1) * 8;

    auto loadStage = [&](int s) {
        uint32_t st = base + (uint32_t)(s % 3) * STG;
        const __half* Ak = A + (long long)s * 64;
        const __half* Wk = W + (long long)s * 64;
#pragma unroll
        for (int j = 0; j < 2; j++) {
            int c = tid + j * 256;
            int r = c >> 3, kq = (c & 7) * 8;
            cpa16(st + (uint32_t)r * 144u + (uint32_t)kq * 2u,
                  Ak + (long long)(m0 + r) * lda + kq);
        }
        uint32_t bs = st + A_BYTES;
#pragma unroll
        for (int j = 0; j < 4; j++) {
            int c = tid + j * 256;
            int r = c >> 3, kq = (c & 7) * 8;
            cpa16(bs + (uint32_t)r * 144u + (uint32_t)kq * 2u,
                  Wk + (long long)(n0 + r) * ldw + kq);
        }
        cpa_commit();
    };

    loadStage(0);
    loadStage(1);

    for (int s = 0; s < S; s++) {
        if (s == S - 1) cpa_wait<0>(); else cpa_wait<1>();
        __syncthreads();
        if (s + 2 < S) loadStage(s + 2);
        else cpa_commit();

        uint32_t aB = base + (uint32_t)(s % 3) * STG;
        uint32_t bB = aB + A_BYTES;

        unsigned afr[2][2][4], bfr[2][2][4];
        // fragment addresses for a given ks
        auto loadFrag = [&](int ks, int buf) {
            int kb = ks * 16;
#pragma unroll
            for (int mt = 0; mt < 2; mt++)
                ldsm_x4(afr[buf][mt],
                        aB + (uint32_t)(wm + mt * 16 + aRow) * 144u
                           + (uint32_t)(kb + aK) * 2u);
#pragma unroll
            for (int p = 0; p < 2; p++)
                ldsm_x4(bfr[buf][p],
                        bB + (uint32_t)(wn + p * 16 + bRow) * 144u
                           + (uint32_t)(kb + bK) * 2u);
        };

        loadFrag(0, 0);
#pragma unroll
        for (int ks = 0; ks < 4; ks++) {
            int buf = ks & 1;
            if (ks < 3) loadFrag(ks + 1, buf ^ 1);
#pragma unroll
            for (int mt = 0; mt < 2; mt++) {
#pragma unroll
                for (int nt = 0; nt < 4; nt++) {
                    // b regs: pair p = nt>>1; lo/hi pair within = (nt&1)*2
                    mma16h(acc[mt][nt], afr[buf][mt], &bfr[buf][nt >> 1][(nt & 1) * 2]);
                }
            }
        }
        __syncthreads();
    }

    float* C32p = C32 ? C32 + blockIdx.z * cZ : (float*)0;
    __half* C16p = C16 ? C16 + blockIdx.z * cZ : (__half*)0;
#pragma unroll
    for (int mt = 0; mt < 2; mt++) {
#pragma unroll
        for (int nt = 0; nt < 4; nt++) {
            int col = n0 + wn + nt * 8 + 2 * tg;
            float b0 = 0.f, b1 = 0.f;
            if (Bias) { b0 = Bias[col]; b1 = Bias[col + 1]; }
            int row = m0 + wm + mt * 16 + g;
            float v00 = acc[mt][nt][0] * alpha + b0;
            float v01 = acc[mt][nt][1] * alpha + b1;
            float v10 = acc[mt][nt][2] * alpha + b0;
            float v11 = acc[mt][nt][3] * alpha + b1;
            if (relu) {
                v00 = fmaxf(v00, 0.f); v01 = fmaxf(v01, 0.f);
                v10 = fmaxf(v10, 0.f); v11 = fmaxf(v11, 0.f);
            }
            if (C32p) {
                *(float2*)&C32p[(long long)row * ldc + col] = make_float2(v00, v01);
                *(float2*)&C32p[(long long)(row + 8) * ldc + col] = make_float2(v10, v11);
            }
            if (C16p) {
                *(__half2*)&C16p[(long long)row * ldc + col] = __floats2half2_rn(v00, v01);
                *(__half2*)&C16p[(long long)(row + 8) * ldc + col] = __floats2half2_rn(v10, v11);
            }
        }
    }
}

// ============ NN GEMM (attn @ V): fp32 in, fp16 out. 64x64 tile. ============
#define SPAD 20
__global__ void __launch_bounds__(128) tf32_nn(
    const float* __restrict__ A, int lda, long long aZ,
    const float* __restrict__ B, int ldb, long long bZ,
    __half* __restrict__ C16, int ldc, long long cZ,
    int K)
{
    A += blockIdx.z * aZ; B += blockIdx.z * bZ; C16 += blockIdx.z * cZ;
    __shared__ unsigned As[2][64 * SPAD];
    __shared__ unsigned Bs[2][64 * SPAD];
    int tid = threadIdx.x;
    int warp = tid >> 5, lane = tid & 31;
    int g = lane >> 2, tg = lane & 3;
    int wm = (warp >> 1) * 32, wn = (warp & 1) * 32;
    int m0 = blockIdx.y * 64, n0 = blockIdx.x * 64;

    int lrow = tid >> 1;
    int lcol = (tid & 1) * 8;
    const float* Ap = A + (long long)(m0 + lrow) * lda + lcol;
    int sidx = lrow * SPAD + lcol;

    int f0 = tid * 2;
    int bk0 = f0 >> 4, bc0 = (f0 & 15) * 4;
    int bk1 = (f0 + 1) >> 4, bc1 = ((f0 + 1) & 15) * 4;
    const float* Bp0 = B + (long long)bk0 * ldb + n0 + bc0;
    const float* Bp1 = B + (long long)bk1 * ldb + n0 + bc1;

    float acc[2][4][4] = {};
    int ntile = K / 16;
    {
        float4 a0 = *(const float4*)(Ap);
        float4 a1 = *(const float4*)(Ap + 4);
        float4 v0 = *(const float4*)(Bp0);
        float4 v1 = *(const float4*)(Bp1);
        *(uint4*)&As[0][sidx]     = make_uint4(f2tf(a0.x), f2tf(a0.y), f2tf(a0.z), f2tf(a0.w));
        *(uint4*)&As[0][sidx + 4] = make_uint4(f2tf(a1.x), f2tf(a1.y), f2tf(a1.z), f2tf(a1.w));
        Bs[0][(bc0 + 0) * SPAD + bk0] = f2tf(v0.x);
        Bs[0][(bc0 + 1) * SPAD + bk0] = f2tf(v0.y);
        Bs[0][(bc0 + 2) * SPAD + bk0] = f2tf(v0.z);
        Bs[0][(bc0 + 3) * SPAD + bk0] = f2tf(v0.w);
        Bs[0][(bc1 + 0) * SPAD + bk1] = f2tf(v1.x);
        Bs[0][(bc1 + 1) * SPAD + bk1] = f2tf(v1.y);
        Bs[0][(bc1 + 2) * SPAD + bk1] = f2tf(v1.z);
        Bs[0][(bc1 + 3) * SPAD + bk1] = f2tf(v1.w);
    }
    __syncthreads();
    int p = 0;
    for (int it = 0; it < ntile; it++) {
        float4 na0, na1, nv0, nv1;
        if (it + 1 < ntile) {
            int ko = (it + 1) * 16;
            na0 = *(const float4*)(Ap + ko);
            na1 = *(const float4*)(Ap + ko + 4);
            nv0 = *(const float4*)(Bp0 + (long long)ko * ldb);
            nv1 = *(const float4*)(Bp1 + (long long)ko * ldb);
        }
#pragma unroll
        for (int ks = 0; ks < 2; ks++) {
            int kb = ks * 8;
            unsigned a[2][4], b[4][2];
#pragma unroll
            for (int mt = 0; mt < 2; mt++) {
                const unsigned* base2 = &As[p][(wm + mt * 16 + g) * SPAD + kb + tg];
                a[mt][0] = base2[0];
                a[mt][1] = base2[8 * SPAD];
                a[mt][2] = base2[4];
                a[mt][3] = base2[8 * SPAD + 4];
            }
#pragma unroll
            for (int nt = 0; nt < 4; nt++) {
                const unsigned* base2 = &Bs[p][(wn + nt * 8 + g) * SPAD + kb + tg];
                b[nt][0] = base2[0];
                b[nt][1] = base2[4];
            }
#pragma unroll
            for (int mt = 0; mt < 2; mt++)
#pragma unroll
                for (int nt = 0; nt < 4; nt++)
                    mma8(acc[mt][nt], a[mt], b[nt]);
        }
        if (it + 1 < ntile) {
            int q = p ^ 1;
            *(uint4*)&As[q][sidx]     = make_uint4(f2tf(na0.x), f2tf(na0.y), f2tf(na0.z), f2tf(na0.w));
            *(uint4*)&As[q][sidx + 4] = make_uint4(f2tf(na1.x), f2tf(na1.y), f2tf(na1.z), f2tf(na1.w));
            Bs[q][(bc0 + 0) * SPAD + bk0] = f2tf(nv0.x);
            Bs[q][(bc0 + 1) * SPAD + bk0] = f2tf(nv0.y);
            Bs[q][(bc0 + 2) * SPAD + bk0] = f2tf(nv0.z);
            Bs[q][(bc0 + 3) * SPAD + bk0] = f2tf(nv0.w);
            Bs[q][(bc1 + 0) * SPAD + bk1] = f2tf(nv1.x);
            Bs[q][(bc1 + 1) * SPAD + bk1] = f2tf(nv1.y);
            Bs[q][(bc1 + 2) * SPAD + bk1] = f2tf(nv1.z);
            Bs[q][(bc1 + 3) * SPAD + bk1] = f2tf(nv1.w);
        }
        __syncthreads();
        p ^= 1;
    }

#pragma unroll
    for (int mt = 0; mt < 2; mt++) {
#pragma unroll
        for (int nt = 0; nt < 4; nt++) {
            int col = n0 + wn + nt * 8 + 2 * tg;
            int row = m0 + wm + mt * 16 + g;
            *(__half2*)&C16[(long long)row * ldc + col] =
                __floats2half2_rn(acc[mt][nt][0], acc[mt][nt][1]);
            *(__half2*)&C16[(long long)(row + 8) * ldc + col] =
                __floats2half2_rn(acc[mt][nt][2], acc[mt][nt][3]);
        }
    }
}

// ---------------- row softmax (fp32) ----------------
__global__ void softmax_rows(float* __restrict__ S, int n) {
    float* row = S + (long long)blockIdx.x * n;
    __shared__ float red[128];
    int tid = threadIdx.x;
    float m = -1e30f;
    for (int j = tid; j < n; j += 128) m = fmaxf(m, row[j]);
    red[tid] = m; __syncthreads();
    for (int off = 64; off; off >>= 1) {
        if (tid < off) red[tid] = fmaxf(red[tid], red[tid + off]);
        __syncthreads();
    }
    m = red[0]; __syncthreads();
    float s = 0.f;
    for (int j = tid; j < n; j += 128) { float e = expf(row[j] - m); row[j] = e; s += e; }
    red[tid] = s; __syncthreads();
    for (int off = 64; off; off >>= 1) {
        if (tid < off) red[tid] += red[tid + off];
        __syncthreads();
    }
    float inv = 1.0f / red[0];
    for (int j = tid; j < n; j += 128) row[j] *= inv;
}

// ---------------- x = LN(x + delta); fp16 shadow ----------------
__global__ void ln_res_kernel(float* __restrict__ x, __half* __restrict__ xh,
                              const float* __restrict__ delta,
                              const float* __restrict__ s, const float* __restrict__ b, int d) {
    float* xr = x + (long long)blockIdx.x * d;
    __half* xhr = xh + (long long)blockIdx.x * d;
    const float* dr = delta + (long long)blockIdx.x * d;
    __shared__ float red[256];
    int tid = threadIdx.x;
    float sum = 0.f;
    for (int j = tid; j < d; j += 256) { float v = xr[j] + dr[j]; xr[j] = v; sum += v; }
    red[tid] = sum; __syncthreads();
    for (int off = 128; off; off >>= 1) {
        if (tid < off) red[tid] += red[tid + off];
        __syncthreads();
    }
    float mean = red[0] / d; __syncthreads();
    float s2 = 0.f;
    for (int j = tid; j < d; j += 256) { float v = xr[j] - mean; s2 += v * v; }
    red[tid] = s2; __syncthreads();
    for (int off = 128; off; off >>= 1) {
        if (tid < off) red[tid] += red[tid + off];
        __syncthreads();
    }
    float inv = rsqrtf(red[0] / d + 1e-5f);
    __syncthreads();
    for (int j = tid; j < d; j += 256) {
        float v = (xr[j] - mean) * inv * s[j] + b[j];
        xr[j] = v;
        xhr[j] = __float2half(v);
    }
}

// ---------------- final linear ----------------
__global__ void lin_kernel(const float* __restrict__ x, const float* __restrict__ w,
                           const float* __restrict__ b, float* __restrict__ a,
                           float* __restrict__ c) {
    int i = blockIdx.x;
    const float* xr = x + (long long)i * CDIM;
    __shared__ float red[4][256];
    int tid = threadIdx.x;
    float s0 = 0, s1 = 0, s2 = 0, s3 = 0;
    for (int k = tid; k < CDIM; k += 256) {
        float xv = xr[k];
        s0 += xv * w[k];
        s1 += xv * w[2 * CDIM + k];
        s2 += xv * w[CDIM + k];
        s3 += xv * w[2 * CDIM + CDIM + k];
    }
    red[0][tid] = s0; red[1][tid] = s1; red[2][tid] = s2; red[3][tid] = s3;
    __syncthreads();
    for (int off = 128; off; off >>= 1) {
        if (tid < off) {
            red[0][tid] += red[0][tid + off];
            red[1][tid] += red[1][tid + off];
            red[2][tid] += red[2][tid + off];
            red[3][tid] += red[3][tid + off];
        }
        __syncthreads();
    }
    if (tid == 0) {
        a[2 * i]     = red[0][0] + b[0];
        a[2 * i + 1] = red[1][0] + b[1];
        c[2 * i]     = red[2][0];
        c[2 * i + 1] = red[3][0];
    }
}

// ---------------- pairwise probs + loss partials ----------------
__global__ void pair_kernel(const float* __restrict__ a, const float* __restrict__ c,
                            const int* __restrict__ gt, float* __restrict__ probs,
                            float* __restrict__ rowcell, float* __restrict__ rowlink) {
    int i = blockIdx.x, j = threadIdx.x;
    float l0 = a[2 * i] + c[2 * j];
    float l1 = a[2 * i + 1] + c[2 * j + 1];
    float m = fmaxf(l0, l1);
    float e0 = expf(l0 - m), e1 = expf(l1 - m);
    float inv = 1.0f / (e0 + e1);
    float p0 = e0 * inv, p1 = e1 * inv;
    long long idx = ((long long)i * N_TOK + j) * 2;
    probs[idx] = p0; probs[idx + 1] = p1;
    float mm = fmaxf(p0, p1);
    float lse = mm + logf(expf(p0 - mm) + expf(p1 - mm));
    float pg = gt[i * N_TOK + j] ? p1 : p0;
    float cell = lse - pg;

    __shared__ float red[512];
    red[j] = cell;
    if (j < 128) red[384 + j] = 0.f;
    __syncthreads();
    for (int off = 256; off; off >>= 1) {
        if (j < off) red[j] += red[j + off];
        __syncthreads();
    }
    if (j == 0) rowcell[i] = red[0];
    __syncthreads();
    red[j] = p1;
    if (j < 128) red[384 + j] = 0.f;
    __syncthreads();
    for (int off = 256; off; off >>= 1) {
        if (j < off) red[j] += red[j + off];
        __syncthreads();
    }
    if (j == 0) rowlink[i] = red[0];
}

__global__ void col_kernel(const float* __restrict__ probs, float* __restrict__ collink) {
    int j = blockIdx.x; int tid = threadIdx.x;
    float s = 0.f;
    for (int i = tid; i < N_TOK; i += 128) s += probs[((long long)i * N_TOK + j) * 2 + 1];
    __shared__ float red[128];
    red[tid] = s; __syncthreads();
    for (int off = 64; off; off >>= 1) {
        if (tid < off) red[tid] += red[tid + off];
        __syncthreads();
    }
    if (tid == 0) collink[j] = red[0];
}

__global__ void final_kernel(const float* __restrict__ rowcell, const float* __restrict__ rowlink,
                             const float* __restrict__ collink, float* __restrict__ out,
                             int out_size) {
    __shared__ float r1[512], r2[512];
    int tid = threadIdx.x;
    r1[tid] = (tid < N_TOK) ? rowcell[tid] : 0.f;
    r2[tid] = (tid < N_TOK - 1) ? fabsf(rowlink[tid] + collink[tid] - 1.0f) : 0.f;
    __syncthreads();
    for (int off = 256; off; off >>= 1) {
        if (tid < off) { r1[tid] += r1[tid + off]; r2[tid] += r2[tid + off]; }
        __syncthreads();
    }
    if (tid == 0 && out_size >= N_TOK * N_TOK * 2 + 2) {
        out[N_TOK * N_TOK * 2]     = r1[0] / (float)N_TOK;
        out[N_TOK * N_TOK * 2 + 1] = r2[0];
    }
}

// ---------------- host orchestration ----------------
struct EncW {
    const __half *qkv_h, *out_h, *ff1_h, *ff2_h;
    const float *qkv_b, *out_b, *ln1_s, *ln1_b, *ff1_b, *ff2_b, *ln2_s, *ln2_b;
};

static void run_encoder(float* x, __half* xh, int d, const EncW& w,
                        float* qkv, __half* qkvh, float* sc, __half* oh,
                        float* y, __half* hh) {
    const int M = N_TOK;
    const int hd = d / NH;
    const float scale = 1.0f / sqrtf((float)hd);
    for (int l = 0; l < NLAYERS; l++) {
        h16_nt<<<dim3(3 * d / 128, M / 64, 1), 256, H_SMEM>>>(
            xh, d, 0, w.qkv_h + (long long)l * 3 * d * d, d, 0,
            w.qkv_b + (long long)l * 3 * d, qkv, qkvh, 3 * d, 0, d, 1.f, 0);
        h16_nt<<<dim3(M / 128, M / 64, NH), 256, H_SMEM>>>(
            qkvh, 3 * d, hd, qkvh + d, 3 * d, hd, (const float*)0,
            sc, (__half*)0, M, (long long)M * M, hd, scale, 0);
        softmax_rows<<<NH * M, 128>>>(sc, M);
        tf32_nn<<<dim3(hd / 64, M / 64, NH), 128>>>(
            sc, M, (long long)M * M, qkv + 2 * d, 3 * d, hd,
            oh, d, hd, M);
        h16_nt<<<dim3(d / 128, M / 64, 1), 256, H_SMEM>>>(
            oh, d, 0, w.out_h + (long long)l * d * d, d, 0,
            w.out_b + (long long)l * d, y, (__half*)0, d, 0, d, 1.f, 0);
        ln_res_kernel<<<M, 256>>>(x, xh, y, w.ln1_s + (long long)l * d, w.ln1_b + (long long)l * d, d);
        h16_nt<<<dim3(FF_DIM / 128, M / 64, 1), 256, H_SMEM>>>(
            xh, d, 0, w.ff1_h + (long long)l * FF_DIM * d, d, 0,
            w.ff1_b + (long long)l * FF_DIM, (float*)0, hh, FF_DIM, 0, d, 1.f, 1);
        h16_nt<<<dim3(d / 128, M / 64, 1), 256, H_SMEM>>>(
            hh, FF_DIM, 0, w.ff2_h + (long long)l * d * FF_DIM, FF_DIM, 0,
            w.ff2_b + (long long)l * d, y, (__half*)0, d, 0, FF_DIM, 1.f, 0);
        ln_res_kernel<<<M, 256>>>(x, xh, y, w.ln2_s + (long long)l * d, w.ln2_b + (long long)l * d, d);
    }
}

extern "C" void kernel_launch(void* const* d_in, const int* in_sizes, int n_in,
                              void* d_out, int out_size) {
    const float* text   = (const float*)d_in[0];
    const float* vision = (const float*)d_in[1];
    const int*   gt     = (const int*)d_in[2];
    const float* lin_w  = (const float*)d_in[27];
    const float* lin_b  = (const float*)d_in[28];

    static int inited = 0;
    if (!inited) {
        cudaFuncSetAttribute(h16_nt, cudaFuncAttributeMaxDynamicSharedMemorySize, H_SMEM);
        inited = 1;
    }

    float* buf = nullptr;
    cudaGetSymbolAddress((void**)&buf, g_buf);
    __half* hb = nullptr;
    cudaGetSymbolAddress((void**)&hb, g_hbuf);

    float* x    = buf + OFF_X;
    float* x2   = buf + OFF_X2;
    float* qkv  = buf + OFF_QKV;
    float* sc   = buf + OFF_SC;
    float* y    = buf + OFF_Y;
    float* ga   = buf + OFF_A;
    float* gc   = buf + OFF_C;
    float* rcel = buf + OFF_RC;
    float* rlnk = buf + OFF_RL;
    float* clnk = buf + OFF_CL;

    __half* qkvh = hb + HA_QKV;
    __half* xh   = hb + HA_X;
    __half* oh   = hb + HA_O;
    __half* hh   = hb + HA_H;

    ConvArgs ca;
    const long long offs[8] = {HW_TQKV, HW_TOUT, HW_TFF1, HW_TFF2,
                               HW_CQKV, HW_COUT, HW_CFF1, HW_CFF2};
    const int srcs[8] = {3, 5, 9, 11, 15, 17, 21, 23};
    const long long ns[8] = {3538944LL, 1179648LL, 3145728LL, 3145728LL,
                             14155776LL, 4718592LL, 6291456LL, 6291456LL};
    ca.cum[0] = 0;
    for (int i = 0; i < 8; i++) {
        ca.src[i] = (const float*)d_in[srcs[i]];
        ca.dstOff[i] = offs[i];
        ca.cum[i + 1] = ca.cum[i] + (int)(ns[i] / 4);
    }
    conv_all<<<(ca.cum[8] + 255) / 256, 256>>>(ca, hb);

    EncW tw = {
        hb + HW_TQKV, hb + HW_TOUT, hb + HW_TFF1, hb + HW_TFF2,
        (const float*)d_in[4], (const float*)d_in[6],
        (const float*)d_in[7], (const float*)d_in[8],
        (const float*)d_in[10], (const float*)d_in[12],
        (const float*)d_in[13], (const float*)d_in[14]
    };
    EncW cw = {
        hb + HW_CQKV, hb + HW_COUT, hb + HW_CFF1, hb + HW_CFF2,
        (const float*)d_in[16], (const float*)d_in[18],
        (const float*)d_in[19], (const float*)d_in[20],
        (const float*)d_in[22], (const float*)d_in[24],
        (const float*)d_in[25], (const float*)d_in[26]
    };

    copy_k<<<(N_TOK * TDIM + 255) / 256, 256>>>(x, xh, text, N_TOK * TDIM);
    run_encoder(x, xh, TDIM, tw, qkv, qkvh, sc, oh, y, hh);

    concat_k<<<(N_TOK * CDIM + 255) / 256, 256>>>(x2, xh, x, vision);
    run_encoder(x2, xh, CDIM, cw, qkv, qkvh, sc, oh, y, hh);

    lin_kernel<<<N_TOK, 256>>>(x2, lin_w, lin_b, ga, gc);

    float* out = (float*)d_out;
    pair_kernel<<<N_TOK, N_TOK>>>(ga, gc, gt, out, rcel, rlnk);
    col_kernel<<<N_TOK, 128>>>(out, clnk);
    final_kernel<<<1, 512>>>(rcel, rlnk, clnk, out, out_size);
}

// round 10
// speedup vs baseline: 2.2809x; 1.0317x over previous
#include <cuda_runtime.h>
#include <cuda_fp16.h>
#include <math.h>
#include <stdint.h>

#define N_TOK 384
#define TDIM 768
#define VDIM 768
#define CDIM 1536
#define FF_DIM 2048
#define NH 4
#define NLAYERS 2

// ---------------- fp32 scratch ----------------
#define OFF_X   0LL
#define OFF_X2  589824LL
#define OFF_QKV 1179648LL
#define OFF_SC  2949120LL
#define OFF_Y   4128768LL
#define OFF_A   5505024LL
#define OFF_C   5505792LL
#define OFF_RC  5506560LL
#define OFF_RL  5506944LL
#define OFF_CL  5507328LL
#define BUF_TOTAL 5507712LL
__device__ float g_buf[BUF_TOTAL];

// ---------------- fp16 scratch ----------------
#define HW_TQKV 0LL
#define HW_TOUT 3538944LL
#define HW_TFF1 4718592LL
#define HW_TFF2 7864320LL
#define HW_CQKV 11010048LL
#define HW_COUT 25165824LL
#define HW_CFF1 29884416LL
#define HW_CFF2 36175872LL
#define HA_QKV  42467328LL
#define HA_X    44236800LL
#define HA_O    44826624LL
#define HA_H    45416448LL
#define HBUF_TOTAL 46202880LL
__device__ __half g_hbuf[HBUF_TOTAL];

// ---------------- PDL ----------------
__device__ __forceinline__ void pdl_wait() {
    asm volatile("griddepcontrol.wait;" ::: "memory");
}
__device__ __forceinline__ void pdl_go() {
    asm volatile("griddepcontrol.launch_dependents;" ::: "memory");
}

// ---------------- helpers ----------------
__device__ __forceinline__ unsigned f2tf(float x) {
    unsigned u;
    asm("cvt.rna.tf32.f32 %0, %1;" : "=r"(u) : "f"(x));
    return u;
}
__device__ __forceinline__ void mma8(float* c, const unsigned* a, const unsigned* b) {
    asm volatile(
        "mma.sync.aligned.m16n8k8.row.col.f32.tf32.tf32.f32 "
        "{%0,%1,%2,%3},{%4,%5,%6,%7},{%8,%9},{%0,%1,%2,%3};"
        : "+f"(c[0]), "+f"(c[1]), "+f"(c[2]), "+f"(c[3])
        : "r"(a[0]), "r"(a[1]), "r"(a[2]), "r"(a[3]), "r"(b[0]), "r"(b[1]));
}
__device__ __forceinline__ void mma16h(float* c, const unsigned* a, const unsigned* b) {
    asm volatile(
        "mma.sync.aligned.m16n8k16.row.col.f32.f16.f16.f32 "
        "{%0,%1,%2,%3},{%4,%5,%6,%7},{%8,%9},{%0,%1,%2,%3};"
        : "+f"(c[0]), "+f"(c[1]), "+f"(c[2]), "+f"(c[3])
        : "r"(a[0]), "r"(a[1]), "r"(a[2]), "r"(a[3]), "r"(b[0]), "r"(b[1]));
}
__device__ __forceinline__ void ldsm_x4(unsigned* r, uint32_t addr) {
    asm volatile("ldmatrix.sync.aligned.m8n8.x4.shared.b16 {%0,%1,%2,%3}, [%4];"
        : "=r"(r[0]), "=r"(r[1]), "=r"(r[2]), "=r"(r[3]) : "r"(addr));
}
__device__ __forceinline__ void cpa16(unsigned dst, const void* src) {
    asm volatile("cp.async.cg.shared.global [%0], [%1], 16;" :: "r"(dst), "l"(src));
}
__device__ __forceinline__ void cpa_commit() { asm volatile("cp.async.commit_group;"); }
template <int N>
__device__ __forceinline__ void cpa_wait() {
    asm volatile("cp.async.wait_group %0;" :: "n"(N));
}

// ---------------- merged weight conversion ----------------
struct ConvArgs {
    const float* src[8];
    long long dstOff[8];
    int cum[9];
};
__global__ void conv_all(ConvArgs a, __half* __restrict__ hbase) {
    int i = blockIdx.x * blockDim.x + threadIdx.x;
    if (i < a.cum[8]) {
#pragma unroll
        for (int k = 0; k < 8; k++) {
            if (i < a.cum[k + 1]) {
                int local = i - a.cum[k];
                float4 v = ((const float4*)a.src[k])[local];
                __half2* d = (__half2*)(hbase + a.dstOff[k]) + local * 2;
                d[0] = __floats2half2_rn(v.x, v.y);
                d[1] = __floats2half2_rn(v.z, v.w);
                break;
            }
        }
    }
    pdl_go();
}

__global__ void copy_k(float* __restrict__ dst, __half* __restrict__ dsth,
                       const float* __restrict__ src, int n) {
    pdl_wait();
    int i = blockIdx.x * blockDim.x + threadIdx.x;
    if (i < n) { float v = src[i]; dst[i] = v; dsth[i] = __float2half(v); }
    pdl_go();
}
__global__ void concat_k(float* __restrict__ dst, __half* __restrict__ dsth,
                         const float* __restrict__ te, const float* __restrict__ vis) {
    pdl_wait();
    int i = blockIdx.x * blockDim.x + threadIdx.x;
    if (i < N_TOK * CDIM) {
        int r = i / CDIM, c = i % CDIM;
        float v = (c < TDIM) ? te[r * TDIM + c] : vis[r * VDIM + (c - TDIM)];
        dst[i] = v; dsth[i] = __float2half(v);
    }
    pdl_go();
}

// ============ fp16 NT GEMM: C = alpha*A(MxK,row)@W(NxK,row)^T + bias ========
#define HPAD 72
#define A_BYTES (64 * HPAD * 2)
#define B_BYTES (128 * HPAD * 2)
#define STG (A_BYTES + B_BYTES)
#define H_SMEM (3 * STG)

__global__ void __launch_bounds__(256) h16_nt(
    const __half* __restrict__ A, int lda, long long aZ,
    const __half* __restrict__ W, int ldw, long long wZ,
    const float* __restrict__ Bias,
    float* __restrict__ C32, __half* __restrict__ C16,
    int ldc, long long cZ,
    int K, float alpha, int relu)
{
    extern __shared__ __half hsm[];
    uint32_t base = (uint32_t)__cvta_generic_to_shared(hsm);

    pdl_wait();
    A += blockIdx.z * aZ; W += blockIdx.z * wZ;

    int tid = threadIdx.x;
    int warp = tid >> 5, lane = tid & 31;
    int g = lane >> 2, tg = lane & 3;
    int wm = (warp >> 2) * 32, wn = (warp & 3) * 32;
    int m0 = blockIdx.y * 64, n0 = blockIdx.x * 128;

    int S = K / 64;
    float acc[2][4][4] = {};

    int aRow = (lane & 7) + ((lane >> 3) & 1) * 8;
    int aK   = ((lane >> 4) & 1) * 8;
    int bRow = ((lane >> 4) & 1) * 8 + (lane & 7);
    int bK   = ((lane >> 3) & 1) * 8;

    auto loadStage = [&](int s) {
        uint32_t st = base + (uint32_t)(s % 3) * STG;
        const __half* Ak = A + (long long)s * 64;
        const __half* Wk = W + (long long)s * 64;
#pragma unroll
        for (int j = 0; j < 2; j++) {
            int c = tid + j * 256;
            int r = c >> 3, kq = (c & 7) * 8;
            cpa16(st + (uint32_t)r * 144u + (uint32_t)kq * 2u,
                  Ak + (long long)(m0 + r) * lda + kq);
        }
        uint32_t bs = st + A_BYTES;
#pragma unroll
        for (int j = 0; j < 4; j++) {
            int c = tid + j * 256;
            int r = c >> 3, kq = (c & 7) * 8;
            cpa16(bs + (uint32_t)r * 144u + (uint32_t)kq * 2u,
                  Wk + (long long)(n0 + r) * ldw + kq);
        }
        cpa_commit();
    };

    loadStage(0);
    loadStage(1);

    for (int s = 0; s < S; s++) {
        if (s == S - 1) cpa_wait<0>(); else cpa_wait<1>();
        __syncthreads();
        if (s + 2 < S) loadStage(s + 2);
        else cpa_commit();

        uint32_t aB = base + (uint32_t)(s % 3) * STG;
        uint32_t bB = aB + A_BYTES;

        unsigned afr[2][2][4], bfr[2][2][4];
        auto loadFrag = [&](int ks, int buf) {
            int kb = ks * 16;
#pragma unroll
            for (int mt = 0; mt < 2; mt++)
                ldsm_x4(afr[buf][mt],
                        aB + (uint32_t)(wm + mt * 16 + aRow) * 144u
                           + (uint32_t)(kb + aK) * 2u);
#pragma unroll
            for (int p = 0; p < 2; p++)
                ldsm_x4(bfr[buf][p],
                        bB + (uint32_t)(wn + p * 16 + bRow) * 144u
                           + (uint32_t)(kb + bK) * 2u);
        };

        loadFrag(0, 0);
#pragma unroll
        for (int ks = 0; ks < 4; ks++) {
            int buf = ks & 1;
            if (ks < 3) loadFrag(ks + 1, buf ^ 1);
#pragma unroll
            for (int mt = 0; mt < 2; mt++) {
#pragma unroll
                for (int nt = 0; nt < 4; nt++) {
                    mma16h(acc[mt][nt], afr[buf][mt], &bfr[buf][nt >> 1][(nt & 1) * 2]);
                }
            }
        }
        __syncthreads();
    }

    float* C32p = C32 ? C32 + blockIdx.z * cZ : (float*)0;
    __half* C16p = C16 ? C16 + blockIdx.z * cZ : (__half*)0;
#pragma unroll
    for (int mt = 0; mt < 2; mt++) {
#pragma unroll
        for (int nt = 0; nt < 4; nt++) {
            int col = n0 + wn + nt * 8 + 2 * tg;
            float b0 = 0.f, b1 = 0.f;
            if (Bias) { b0 = Bias[col]; b1 = Bias[col + 1]; }
            int row = m0 + wm + mt * 16 + g;
            float v00 = acc[mt][nt][0] * alpha + b0;
            float v01 = acc[mt][nt][1] * alpha + b1;
            float v10 = acc[mt][nt][2] * alpha + b0;
            float v11 = acc[mt][nt][3] * alpha + b1;
            if (relu) {
                v00 = fmaxf(v00, 0.f); v01 = fmaxf(v01, 0.f);
                v10 = fmaxf(v10, 0.f); v11 = fmaxf(v11, 0.f);
            }
            if (C32p) {
                *(float2*)&C32p[(long long)row * ldc + col] = make_float2(v00, v01);
                *(float2*)&C32p[(long long)(row + 8) * ldc + col] = make_float2(v10, v11);
            }
            if (C16p) {
                *(__half2*)&C16p[(long long)row * ldc + col] = __floats2half2_rn(v00, v01);
                *(__half2*)&C16p[(long long)(row + 8) * ldc + col] = __floats2half2_rn(v10, v11);
            }
        }
    }
    pdl_go();
}

// ============ NN GEMM (attn @ V): fp32 in, fp16 out. 64x64 tile. ============
#define SPAD 20
__global__ void __launch_bounds__(128) tf32_nn(
    const float* __restrict__ A, int lda, long long aZ,
    const float* __restrict__ B, int ldb, long long bZ,
    __half* __restrict__ C16, int ldc, long long cZ,
    int K)
{
    pdl_wait();
    A += blockIdx.z * aZ; B += blockIdx.z * bZ; C16 += blockIdx.z * cZ;
    __shared__ unsigned As[2][64 * SPAD];
    __shared__ unsigned Bs[2][64 * SPAD];
    int tid = threadIdx.x;
    int warp = tid >> 5, lane = tid & 31;
    int g = lane >> 2, tg = lane & 3;
    int wm = (warp >> 1) * 32, wn = (warp & 1) * 32;
    int m0 = blockIdx.y * 64, n0 = blockIdx.x * 64;

    int lrow = tid >> 1;
    int lcol = (tid & 1) * 8;
    const float* Ap = A + (long long)(m0 + lrow) * lda + lcol;
    int sidx = lrow * SPAD + lcol;

    int f0 = tid * 2;
    int bk0 = f0 >> 4, bc0 = (f0 & 15) * 4;
    int bk1 = (f0 + 1) >> 4, bc1 = ((f0 + 1) & 15) * 4;
    const float* Bp0 = B + (long long)bk0 * ldb + n0 + bc0;
    const float* Bp1 = B + (long long)bk1 * ldb + n0 + bc1;

    float acc[2][4][4] = {};
    int ntile = K / 16;
    {
        float4 a0 = *(const float4*)(Ap);
        float4 a1 = *(const float4*)(Ap + 4);
        float4 v0 = *(const float4*)(Bp0);
        float4 v1 = *(const float4*)(Bp1);
        *(uint4*)&As[0][sidx]     = make_uint4(f2tf(a0.x), f2tf(a0.y), f2tf(a0.z), f2tf(a0.w));
        *(uint4*)&As[0][sidx + 4] = make_uint4(f2tf(a1.x), f2tf(a1.y), f2tf(a1.z), f2tf(a1.w));
        Bs[0][(bc0 + 0) * SPAD + bk0] = f2tf(v0.x);
        Bs[0][(bc0 + 1) * SPAD + bk0] = f2tf(v0.y);
        Bs[0][(bc0 + 2) * SPAD + bk0] = f2tf(v0.z);
        Bs[0][(bc0 + 3) * SPAD + bk0] = f2tf(v0.w);
        Bs[0][(bc1 + 0) * SPAD + bk1] = f2tf(v1.x);
        Bs[0][(bc1 + 1) * SPAD + bk1] = f2tf(v1.y);
        Bs[0][(bc1 + 2) * SPAD + bk1] = f2tf(v1.z);
        Bs[0][(bc1 + 3) * SPAD + bk1] = f2tf(v1.w);
    }
    __syncthreads();
    int p = 0;
    for (int it = 0; it < ntile; it++) {
        float4 na0, na1, nv0, nv1;
        if (it + 1 < ntile) {
            int ko = (it + 1) * 16;
            na0 = *(const float4*)(Ap + ko);
            na1 = *(const float4*)(Ap + ko + 4);
            nv0 = *(const float4*)(Bp0 + (long long)ko * ldb);
            nv1 = *(const float4*)(Bp1 + (long long)ko * ldb);
        }
#pragma unroll
        for (int ks = 0; ks < 2; ks++) {
            int kb = ks * 8;
            unsigned a[2][4], b[4][2];
#pragma unroll
            for (int mt = 0; mt < 2; mt++) {
                const unsigned* base2 = &As[p][(wm + mt * 16 + g) * SPAD + kb + tg];
                a[mt][0] = base2[0];
                a[mt][1] = base2[8 * SPAD];
                a[mt][2] = base2[4];
                a[mt][3] = base2[8 * SPAD + 4];
            }
#pragma unroll
            for (int nt = 0; nt < 4; nt++) {
                const unsigned* base2 = &Bs[p][(wn + nt * 8 + g) * SPAD + kb + tg];
                b[nt][0] = base2[0];
                b[nt][1] = base2[4];
            }
#pragma unroll
            for (int mt = 0; mt < 2; mt++)
#pragma unroll
                for (int nt = 0; nt < 4; nt++)
                    mma8(acc[mt][nt], a[mt], b[nt]);
        }
        if (it + 1 < ntile) {
            int q = p ^ 1;
            *(uint4*)&As[q][sidx]     = make_uint4(f2tf(na0.x), f2tf(na0.y), f2tf(na0.z), f2tf(na0.w));
            *(uint4*)&As[q][sidx + 4] = make_uint4(f2tf(na1.x), f2tf(na1.y), f2tf(na1.z), f2tf(na1.w));
            Bs[q][(bc0 + 0) * SPAD + bk0] = f2tf(nv0.x);
            Bs[q][(bc0 + 1) * SPAD + bk0] = f2tf(nv0.y);
            Bs[q][(bc0 + 2) * SPAD + bk0] = f2tf(nv0.z);
            Bs[q][(bc0 + 3) * SPAD + bk0] = f2tf(nv0.w);
            Bs[q][(bc1 + 0) * SPAD + bk1] = f2tf(nv1.x);
            Bs[q][(bc1 + 1) * SPAD + bk1] = f2tf(nv1.y);
            Bs[q][(bc1 + 2) * SPAD + bk1] = f2tf(nv1.z);
            Bs[q][(bc1 + 3) * SPAD + bk1] = f2tf(nv1.w);
        }
        __syncthreads();
        p ^= 1;
    }

#pragma unroll
    for (int mt = 0; mt < 2; mt++) {
#pragma unroll
        for (int nt = 0; nt < 4; nt++) {
            int col = n0 + wn + nt * 8 + 2 * tg;
            int row = m0 + wm + mt * 16 + g;
            *(__half2*)&C16[(long long)row * ldc + col] =
                __floats2half2_rn(acc[mt][nt][0], acc[mt][nt][1]);
            *(__half2*)&C16[(long long)(row + 8) * ldc + col] =
                __floats2half2_rn(acc[mt][nt][2], acc[mt][nt][3]);
        }
    }
    pdl_go();
}

// ---------------- row softmax (fp32) ----------------
__global__ void softmax_rows(float* __restrict__ S, int n) {
    pdl_wait();
    float* row = S + (long long)blockIdx.x * n;
    __shared__ float red[128];
    int tid = threadIdx.x;
    float m = -1e30f;
    for (int j = tid; j < n; j += 128) m = fmaxf(m, row[j]);
    red[tid] = m; __syncthreads();
    for (int off = 64; off; off >>= 1) {
        if (tid < off) red[tid] = fmaxf(red[tid], red[tid + off]);
        __syncthreads();
    }
    m = red[0]; __syncthreads();
    float s = 0.f;
    for (int j = tid; j < n; j += 128) { float e = expf(row[j] - m); row[j] = e; s += e; }
    red[tid] = s; __syncthreads();
    for (int off = 64; off; off >>= 1) {
        if (tid < off) red[tid] += red[tid + off];
        __syncthreads();
    }
    float inv = 1.0f / red[0];
    for (int j = tid; j < n; j += 128) row[j] *= inv;
    pdl_go();
}

// ---------------- x = LN(x + delta); fp16 shadow ----------------
__global__ void ln_res_kernel(float* __restrict__ x, __half* __restrict__ xh,
                              const float* __restrict__ delta,
                              const float* __restrict__ s, const float* __restrict__ b, int d) {
    pdl_wait();
    float* xr = x + (long long)blockIdx.x * d;
    __half* xhr = xh + (long long)blockIdx.x * d;
    const float* dr = delta + (long long)blockIdx.x * d;
    __shared__ float red[256];
    int tid = threadIdx.x;
    float sum = 0.f;
    for (int j = tid; j < d; j += 256) { float v = xr[j] + dr[j]; xr[j] = v; sum += v; }
    red[tid] = sum; __syncthreads();
    for (int off = 128; off; off >>= 1) {
        if (tid < off) red[tid] += red[tid + off];
        __syncthreads();
    }
    float mean = red[0] / d; __syncthreads();
    float s2 = 0.f;
    for (int j = tid; j < d; j += 256) { float v = xr[j] - mean; s2 += v * v; }
    red[tid] = s2; __syncthreads();
    for (int off = 128; off; off >>= 1) {
        if (tid < off) red[tid] += red[tid + off];
        __syncthreads();
    }
    float inv = rsqrtf(red[0] / d + 1e-5f);
    __syncthreads();
    for (int j = tid; j < d; j += 256) {
        float v = (xr[j] - mean) * inv * s[j] + b[j];
        xr[j] = v;
        xhr[j] = __float2half(v);
    }
    pdl_go();
}

// ---------------- final linear ----------------
__global__ void lin_kernel(const float* __restrict__ x, const float* __restrict__ w,
                           const float* __restrict__ b, float* __restrict__ a,
                           float* __restrict__ c) {
    pdl_wait();
    int i = blockIdx.x;
    const float* xr = x + (long long)i * CDIM;
    __shared__ float red[4][256];
    int tid = threadIdx.x;
    float s0 = 0, s1 = 0, s2 = 0, s3 = 0;
    for (int k = tid; k < CDIM; k += 256) {
        float xv = xr[k];
        s0 += xv * w[k];
        s1 += xv * w[2 * CDIM + k];
        s2 += xv * w[CDIM + k];
        s3 += xv * w[2 * CDIM + CDIM + k];
    }
    red[0][tid] = s0; red[1][tid] = s1; red[2][tid] = s2; red[3][tid] = s3;
    __syncthreads();
    for (int off = 128; off; off >>= 1) {
        if (tid < off) {
            red[0][tid] += red[0][tid + off];
            red[1][tid] += red[1][tid + off];
            red[2][tid] += red[2][tid + off];
            red[3][tid] += red[3][tid + off];
        }
        __syncthreads();
    }
    if (tid == 0) {
        a[2 * i]     = red[0][0] + b[0];
        a[2 * i + 1] = red[1][0] + b[1];
        c[2 * i]     = red[2][0];
        c[2 * i + 1] = red[3][0];
    }
    pdl_go();
}

// ---------------- pairwise probs + loss partials ----------------
__global__ void pair_kernel(const float* __restrict__ a, const float* __restrict__ c,
                            const int* __restrict__ gt, float* __restrict__ probs,
                            float* __restrict__ rowcell, float* __restrict__ rowlink) {
    pdl_wait();
    int i = blockIdx.x, j = threadIdx.x;
    float l0 = a[2 * i] + c[2 * j];
    float l1 = a[2 * i + 1] + c[2 * j + 1];
    float m = fmaxf(l0, l1);
    float e0 = expf(l0 - m), e1 = expf(l1 - m);
    float inv = 1.0f / (e0 + e1);
    float p0 = e0 * inv, p1 = e1 * inv;
    long long idx = ((long long)i * N_TOK + j) * 2;
    probs[idx] = p0; probs[idx + 1] = p1;
    float mm = fmaxf(p0, p1);
    float lse = mm + logf(expf(p0 - mm) + expf(p1 - mm));
    float pg = gt[i * N_TOK + j] ? p1 : p0;
    float cell = lse - pg;

    __shared__ float red[512];
    red[j] = cell;
    if (j < 128) red[384 + j] = 0.f;
    __syncthreads();
    for (int off = 256; off; off >>= 1) {
        if (j < off) red[j] += red[j + off];
        __syncthreads();
    }
    if (j == 0) rowcell[i] = red[0];
    __syncthreads();
    red[j] = p1;
    if (j < 128) red[384 + j] = 0.f;
    __syncthreads();
    for (int off = 256; off; off >>= 1) {
        if (j < off) red[j] += red[j + off];
        __syncthreads();
    }
    if (j == 0) rowlink[i] = red[0];
    pdl_go();
}

__global__ void col_kernel(const float* __restrict__ probs, float* __restrict__ collink) {
    pdl_wait();
    int j = blockIdx.x; int tid = threadIdx.x;
    float s = 0.f;
    for (int i = tid; i < N_TOK; i += 128) s += probs[((long long)i * N_TOK + j) * 2 + 1];
    __shared__ float red[128];
    red[tid] = s; __syncthreads();
    for (int off = 64; off; off >>= 1) {
        if (tid < off) red[tid] += red[tid + off];
        __syncthreads();
    }
    if (tid == 0) collink[j] = red[0];
    pdl_go();
}

__global__ void final_kernel(const float* __restrict__ rowcell, const float* __restrict__ rowlink,
                             const float* __restrict__ collink, float* __restrict__ out,
                             int out_size) {
    pdl_wait();
    __shared__ float r1[512], r2[512];
    int tid = threadIdx.x;
    r1[tid] = (tid < N_TOK) ? rowcell[tid] : 0.f;
    r2[tid] = (tid < N_TOK - 1) ? fabsf(rowlink[tid] + collink[tid] - 1.0f) : 0.f;
    __syncthreads();
    for (int off = 256; off; off >>= 1) {
        if (tid < off) { r1[tid] += r1[tid + off]; r2[tid] += r2[tid + off]; }
        __syncthreads();
    }
    if (tid == 0 && out_size >= N_TOK * N_TOK * 2 + 2) {
        out[N_TOK * N_TOK * 2]     = r1[0] / (float)N_TOK;
        out[N_TOK * N_TOK * 2 + 1] = r2[0];
    }
}

// ---------------- host orchestration (PDL launches) ----------------
static cudaLaunchAttribute g_attr[1];
template <typename F, typename... Args>
static inline void pl(F f, dim3 gr, dim3 bl, size_t sm, Args... args) {
    cudaLaunchConfig_t c = {};
    c.gridDim = gr; c.blockDim = bl; c.dynamicSmemBytes = sm; c.stream = 0;
    g_attr[0].id = cudaLaunchAttributeProgrammaticStreamSerialization;
    g_attr[0].val.programmaticStreamSerializationAllowed = 1;
    c.attrs = g_attr; c.numAttrs = 1;
    cudaLaunchKernelEx(&c, f, args...);
}

struct EncW {
    const __half *qkv_h, *out_h, *ff1_h, *ff2_h;
    const float *qkv_b, *out_b, *ln1_s, *ln1_b, *ff1_b, *ff2_b, *ln2_s, *ln2_b;
};

static void run_encoder(float* x, __half* xh, int d, const EncW& w,
                        float* qkv, __half* qkvh, float* sc, __half* oh,
                        float* y, __half* hh) {
    const int M = N_TOK;
    const int hd = d / NH;
    const float scale = 1.0f / sqrtf((float)hd);
    for (int l = 0; l < NLAYERS; l++) {
        pl(h16_nt, dim3(3 * d / 128, M / 64, 1), dim3(256), H_SMEM,
           (const __half*)xh, d, 0LL, w.qkv_h + (long long)l * 3 * d * d, d, 0LL,
           w.qkv_b + (long long)l * 3 * d, qkv, qkvh, 3 * d, 0LL, d, 1.f, 0);
        pl(h16_nt, dim3(M / 128, M / 64, NH), dim3(256), H_SMEM,
           (const __half*)qkvh, 3 * d, (long long)hd, (const __half*)(qkvh + d), 3 * d, (long long)hd,
           (const float*)0, sc, (__half*)0, M, (long long)M * M, hd, scale, 0);
        pl(softmax_rows, dim3(NH * M), dim3(128), 0, sc, M);
        pl(tf32_nn, dim3(hd / 64, M / 64, NH), dim3(128), 0,
           (const float*)sc, M, (long long)M * M, (const float*)(qkv + 2 * d), (long long)(3 * d), (long long)hd,
           oh, d, (long long)hd, M);
        pl(h16_nt, dim3(d / 128, M / 64, 1), dim3(256), H_SMEM,
           (const __half*)oh, d, 0LL, w.out_h + (long long)l * d * d, d, 0LL,
           w.out_b + (long long)l * d, y, (__half*)0, d, 0LL, d, 1.f, 0);
        pl(ln_res_kernel, dim3(M), dim3(256), 0,
           x, xh, (const float*)y, w.ln1_s + (long long)l * d, w.ln1_b + (long long)l * d, d);
        pl(h16_nt, dim3(FF_DIM / 128, M / 64, 1), dim3(256), H_SMEM,
           (const __half*)xh, d, 0LL, w.ff1_h + (long long)l * FF_DIM * d, d, 0LL,
           w.ff1_b + (long long)l * FF_DIM, (float*)0, hh, FF_DIM, 0LL, d, 1.f, 1);
        pl(h16_nt, dim3(d / 128, M / 64, 1), dim3(256), H_SMEM,
           (const __half*)hh, FF_DIM, 0LL, w.ff2_h + (long long)l * d * FF_DIM, FF_DIM, 0LL,
           w.ff2_b + (long long)l * d, y, (__half*)0, d, 0LL, FF_DIM, 1.f, 0);
        pl(ln_res_kernel, dim3(M), dim3(256), 0,
           x, xh, (const float*)y, w.ln2_s + (long long)l * d, w.ln2_b + (long long)l * d, d);
    }
}

extern "C" void kernel_launch(void* const* d_in, const int* in_sizes, int n_in,
                              void* d_out, int out_size) {
    const float* text   = (const float*)d_in[0];
    const float* vision = (const float*)d_in[1];
    const int*   gt     = (const int*)d_in[2];
    const float* lin_w  = (const float*)d_in[27];
    const float* lin_b  = (const float*)d_in[28];

    static int inited = 0;
    if (!inited) {
        cudaFuncSetAttribute(h16_nt, cudaFuncAttributeMaxDynamicSharedMemorySize, H_SMEM);
        inited = 1;
    }

    float* buf = nullptr;
    cudaGetSymbolAddress((void**)&buf, g_buf);
    __half* hb = nullptr;
    cudaGetSymbolAddress((void**)&hb, g_hbuf);

    float* x    = buf + OFF_X;
    float* x2   = buf + OFF_X2;
    float* qkv  = buf + OFF_QKV;
    float* sc   = buf + OFF_SC;
    float* y    = buf + OFF_Y;
    float* ga   = buf + OFF_A;
    float* gc   = buf + OFF_C;
    float* rcel = buf + OFF_RC;
    float* rlnk = buf + OFF_RL;
    float* clnk = buf + OFF_CL;

    __half* qkvh = hb + HA_QKV;
    __half* xh   = hb + HA_X;
    __half* oh   = hb + HA_O;
    __half* hh   = hb + HA_H;

    ConvArgs ca;
    const long long offs[8] = {HW_TQKV, HW_TOUT, HW_TFF1, HW_TFF2,
                               HW_CQKV, HW_COUT, HW_CFF1, HW_CFF2};
    const int srcs[8] = {3, 5, 9, 11, 15, 17, 21, 23};
    const long long ns[8] = {3538944LL, 1179648LL, 3145728LL, 3145728LL,
                             14155776LL, 4718592LL, 6291456LL, 6291456LL};
    ca.cum[0] = 0;
    for (int i = 0; i < 8; i++) {
        ca.src[i] = (const float*)d_in[srcs[i]];
        ca.dstOff[i] = offs[i];
        ca.cum[i + 1] = ca.cum[i] + (int)(ns[i] / 4);
    }
    pl(conv_all, dim3((ca.cum[8] + 255) / 256), dim3(256), 0, ca, hb);

    EncW tw = {
        hb + HW_TQKV, hb + HW_TOUT, hb + HW_TFF1, hb + HW_TFF2,
        (const float*)d_in[4], (const float*)d_in[6],
        (const float*)d_in[7], (const float*)d_in[8],
        (const float*)d_in[10], (const float*)d_in[12],
        (const float*)d_in[13], (const float*)d_in[14]
    };
    EncW cw = {
        hb + HW_CQKV, hb + HW_COUT, hb + HW_CFF1, hb + HW_CFF2,
        (const float*)d_in[16], (const float*)d_in[18],
        (const float*)d_in[19], (const float*)d_in[20],
        (const float*)d_in[22], (const float*)d_in[24],
        (const float*)d_in[25], (const float*)d_in[26]
    };

    pl(copy_k, dim3((N_TOK * TDIM + 255) / 256), dim3(256), 0, x, xh, text, N_TOK * TDIM);
    run_encoder(x, xh, TDIM, tw, qkv, qkvh, sc, oh, y, hh);

    pl(concat_k, dim3((N_TOK * CDIM + 255) / 256), dim3(256), 0, x2, xh, (const float*)x, vision);
    run_encoder(x2, xh, CDIM, cw, qkv, qkvh, sc, oh, y, hh);

    pl(lin_kernel, dim3(N_TOK), dim3(256), 0, (const float*)x2, lin_w, lin_b, ga, gc);

    float* out = (float*)d_out;
    pl(pair_kernel, dim3(N_TOK), dim3(N_TOK), 0,
       (const float*)ga, (const float*)gc, gt, out, rcel, rlnk);
    pl(col_kernel, dim3(N_TOK), dim3(128), 0, (const float*)out, clnk);
    pl(final_kernel, dim3(1), dim3(512), 0,
       (const float*)rcel, (const float*)rlnk, (const float*)clnk, out, out_size);
}